// round 8
// baseline (speedup 1.0000x reference)
#include <cuda_runtime.h>
#include <cuda_bf16.h>
#include <cstdint>

#define BATCH 512
#define SEQ   256
#define EMBED 384
#define HDIM  64
#define NROWS (BATCH * SEQ)   // 131072

typedef uint16_t half_t;

// ---------------------------------------------------------------------------
// Global scratch: projected Q/K/V in split bf16.
//   Qh/Ql, Kh/Kl: [b][s][d]   (row.col mma layout for S = Q K^T)
//   Vth/Vtl:      [b][d][s]   (B operand layout for O = P V)
// ---------------------------------------------------------------------------
__device__ half_t g_Qh[(size_t)NROWS * HDIM];
__device__ half_t g_Ql[(size_t)NROWS * HDIM];
__device__ half_t g_Kh[(size_t)NROWS * HDIM];
__device__ half_t g_Kl[(size_t)NROWS * HDIM];
__device__ half_t g_Vth[(size_t)BATCH * HDIM * SEQ];
__device__ half_t g_Vtl[(size_t)BATCH * HDIM * SEQ];

// ---------------------------------------------------------------------------
__device__ __forceinline__ void mma_bf16(float* d, const uint32_t* a,
                                         uint32_t b0, uint32_t b1) {
    asm volatile(
        "mma.sync.aligned.m16n8k16.row.col.f32.bf16.bf16.f32 "
        "{%0,%1,%2,%3}, {%4,%5,%6,%7}, {%8,%9}, {%0,%1,%2,%3};"
        : "+f"(d[0]), "+f"(d[1]), "+f"(d[2]), "+f"(d[3])
        : "r"(a[0]), "r"(a[1]), "r"(a[2]), "r"(a[3]), "r"(b0), "r"(b1));
}

__device__ __forceinline__ void ldsm_x4(uint32_t& r0, uint32_t& r1,
                                        uint32_t& r2, uint32_t& r3,
                                        uint32_t addr) {
    asm volatile(
        "ldmatrix.sync.aligned.m8n8.x4.shared.b16 {%0,%1,%2,%3}, [%4];"
        : "=r"(r0), "=r"(r1), "=r"(r2), "=r"(r3) : "r"(addr));
}

__device__ __forceinline__ void split2(float x, float y, uint32_t& h, uint32_t& l) {
    const __nv_bfloat162 hh = __floats2bfloat162_rn(x, y);
    const __nv_bfloat162 ll = __floats2bfloat162_rn(
        x - __bfloat162float(hh.x), y - __bfloat162float(hh.y));
    h = *(const uint32_t*)&hh;
    l = *(const uint32_t*)&ll;
}

// ---------------------------------------------------------------------------
// Projection via HMMA: per CTA M=128, N=192 (Q|K|V), K=384 in 6 chunks of 64.
// 8 warps = 4(m) x 2(n); warp tile 32 x 96. acc += Ah*Bh + Ah*Bl + Al*Bh.
// W fp32 is split to bf16 on the fly in the B loader (W stays L2-resident).
// Epilogue: stage fp32 in smem, emit split-bf16 Q/K [b][s][d], V^T [b][d][s].
// ---------------------------------------------------------------------------
#define AK_LD 72
#define OFF_AH 0
#define OFF_AL (OFF_AH + 128 * AK_LD)
#define OFF_BH (OFF_AL + 128 * AK_LD)
#define OFF_BL (OFF_BH + 192 * AK_LD)
#define MMA_SMEM_HALVES (OFF_BL + 192 * AK_LD)
#define ST_LD 196
#define PJ_SMEM_BYTES (128 * ST_LD * 4 > MMA_SMEM_HALVES * 2 ? 128 * ST_LD * 4 : MMA_SMEM_HALVES * 2)

__global__ __launch_bounds__(256) void proj_kernel(
    const float* __restrict__ X,
    const float* __restrict__ Wq,
    const float* __restrict__ Wk,
    const float* __restrict__ Wv)
{
    extern __shared__ char smraw[];
    half_t* Ah = (half_t*)(smraw) + OFF_AH;
    half_t* Al = (half_t*)(smraw) + OFF_AL;
    half_t* Bh = (half_t*)(smraw) + OFF_BH;
    half_t* Bl = (half_t*)(smraw) + OFF_BL;
    float*  stage = (float*)smraw;

    const int tid = threadIdx.x;
    const int lane = tid & 31;
    const int wid = tid >> 5;
    const int warp_m = wid & 3;
    const int warp_n = wid >> 2;
    const int row0 = blockIdx.x * 128;

    float acc[2][12][4];
#pragma unroll
    for (int mt = 0; mt < 2; ++mt)
#pragma unroll
        for (int nt = 0; nt < 12; ++nt)
#pragma unroll
            for (int i = 0; i < 4; ++i) acc[mt][nt][i] = 0.0f;

    const int r_fr = lane >> 2;
    const int c_fr = (lane & 3) * 2;

    for (int c = 0; c < 6; ++c) {
        // --- A: X[128][64] fp32 -> split bf16 ---
#pragma unroll
        for (int i = 0; i < 8; ++i) {
            const int idx = i * 256 + tid;
            const int m = idx >> 4;
            const int c4 = (idx & 15) * 4;
            const float4 v = *(const float4*)(X + (size_t)(row0 + m) * EMBED + c * 64 + c4);
            uint32_t h0, l0, h1, l1;
            split2(v.x, v.y, h0, l0);
            split2(v.z, v.w, h1, l1);
            uint2 hv, lv;
            hv.x = h0; hv.y = h1; lv.x = l0; lv.y = l1;
            *(uint2*)(Ah + m * AK_LD + c4) = hv;
            *(uint2*)(Al + m * AK_LD + c4) = lv;
        }
        // --- B: W fp32 [k][n] -> split bf16 [n][k] smem (on-the-fly wconv) ---
#pragma unroll
        for (int i = 0; i < 12; ++i) {
            const int idx = i * 256 + tid;       // 3072 total
            const int n = idx >> 4;              // fused col 0..191
            const int q4 = (idx & 15) * 4;       // k offset within chunk
            const int mat = n >> 6;
            const float* W = (mat == 0) ? Wq : ((mat == 1) ? Wk : Wv);
            const int nn = n & 63;
            const int kg = c * 64 + q4;
            const float v0 = W[(size_t)(kg + 0) * HDIM + nn];
            const float v1 = W[(size_t)(kg + 1) * HDIM + nn];
            const float v2 = W[(size_t)(kg + 2) * HDIM + nn];
            const float v3 = W[(size_t)(kg + 3) * HDIM + nn];
            uint32_t h0, l0, h1, l1;
            split2(v0, v1, h0, l0);
            split2(v2, v3, h1, l1);
            uint2 hv, lv; hv.x = h0; hv.y = h1; lv.x = l0; lv.y = l1;
            *(uint2*)(Bh + n * AK_LD + q4) = hv;
            *(uint2*)(Bl + n * AK_LD + q4) = lv;
        }
        __syncthreads();

#pragma unroll
        for (int ks = 0; ks < 4; ++ks) {
            const int kc = ks * 16 + c_fr;
            uint32_t ah[2][4], al[2][4];
#pragma unroll
            for (int mt = 0; mt < 2; ++mt) {
                const int mb = warp_m * 32 + mt * 16;
                ah[mt][0] = *(const uint32_t*)(Ah + (mb + r_fr) * AK_LD + kc);
                ah[mt][1] = *(const uint32_t*)(Ah + (mb + r_fr + 8) * AK_LD + kc);
                ah[mt][2] = *(const uint32_t*)(Ah + (mb + r_fr) * AK_LD + kc + 8);
                ah[mt][3] = *(const uint32_t*)(Ah + (mb + r_fr + 8) * AK_LD + kc + 8);
                al[mt][0] = *(const uint32_t*)(Al + (mb + r_fr) * AK_LD + kc);
                al[mt][1] = *(const uint32_t*)(Al + (mb + r_fr + 8) * AK_LD + kc);
                al[mt][2] = *(const uint32_t*)(Al + (mb + r_fr) * AK_LD + kc + 8);
                al[mt][3] = *(const uint32_t*)(Al + (mb + r_fr + 8) * AK_LD + kc + 8);
            }
#pragma unroll
            for (int nt = 0; nt < 12; ++nt) {
                const int nb = warp_n * 96 + nt * 8 + r_fr;
                const uint32_t bh0 = *(const uint32_t*)(Bh + nb * AK_LD + kc);
                const uint32_t bh1 = *(const uint32_t*)(Bh + nb * AK_LD + kc + 8);
                const uint32_t bl0 = *(const uint32_t*)(Bl + nb * AK_LD + kc);
                const uint32_t bl1 = *(const uint32_t*)(Bl + nb * AK_LD + kc + 8);
                mma_bf16(acc[0][nt], ah[0], bh0, bh1);
                mma_bf16(acc[1][nt], ah[1], bh0, bh1);
                mma_bf16(acc[0][nt], ah[0], bl0, bl1);
                mma_bf16(acc[1][nt], ah[1], bl0, bl1);
                mma_bf16(acc[0][nt], al[0], bh0, bh1);
                mma_bf16(acc[1][nt], al[1], bh0, bh1);
            }
        }
        __syncthreads();
    }

#pragma unroll
    for (int mt = 0; mt < 2; ++mt) {
        const int r0 = warp_m * 32 + mt * 16 + r_fr;
#pragma unroll
        for (int nt = 0; nt < 12; ++nt) {
            const int col = warp_n * 96 + nt * 8 + c_fr;
            float2 v0, v1;
            v0.x = acc[mt][nt][0]; v0.y = acc[mt][nt][1];
            v1.x = acc[mt][nt][2]; v1.y = acc[mt][nt][3];
            *(float2*)(stage + r0 * ST_LD + col)       = v0;
            *(float2*)(stage + (r0 + 8) * ST_LD + col) = v1;
        }
    }
    __syncthreads();

    const int b = row0 >> 8;
    const int sbase = row0 & 255;

    for (int idx = tid; idx < 2048; idx += 256) {
        const int m = idx >> 4;
        const int q = (idx & 15) * 4;
        const size_t go = (size_t)(row0 + m) * HDIM + q;
        {
            const float4 v = *(const float4*)(stage + m * ST_LD + q);
            uint32_t h0, l0, h1, l1;
            split2(v.x, v.y, h0, l0);
            split2(v.z, v.w, h1, l1);
            uint2 hv, lv; hv.x = h0; hv.y = h1; lv.x = l0; lv.y = l1;
            *(uint2*)(g_Qh + go) = hv;
            *(uint2*)(g_Ql + go) = lv;
        }
        {
            const float4 v = *(const float4*)(stage + m * ST_LD + 64 + q);
            uint32_t h0, l0, h1, l1;
            split2(v.x, v.y, h0, l0);
            split2(v.z, v.w, h1, l1);
            uint2 hv, lv; hv.x = h0; hv.y = h1; lv.x = l0; lv.y = l1;
            *(uint2*)(g_Kh + go) = hv;
            *(uint2*)(g_Kl + go) = lv;
        }
    }
    for (int idx = tid; idx < 2048; idx += 256) {
        const int d = idx >> 5;
        const int s0 = (idx & 31) * 4;
        float v0 = stage[(s0 + 0) * ST_LD + 128 + d];
        float v1 = stage[(s0 + 1) * ST_LD + 128 + d];
        float v2 = stage[(s0 + 2) * ST_LD + 128 + d];
        float v3 = stage[(s0 + 3) * ST_LD + 128 + d];
        uint32_t h0, l0, h1, l1;
        split2(v0, v1, h0, l0);
        split2(v2, v3, h1, l1);
        uint2 hv, lv; hv.x = h0; hv.y = h1; lv.x = l0; lv.y = l1;
        const size_t go = ((size_t)b * HDIM + d) * SEQ + sbase + s0;
        *(uint2*)(g_Vth + go) = hv;
        *(uint2*)(g_Vtl + go) = lv;
    }
}

// ---------------------------------------------------------------------------
// FlashAttention-2 attention (split-bf16, 3 passes). Grid (2, 512).
// B-fragments loaded via ldmatrix.x4 (hi0, hi1, lo0, lo1 in one LDSM).
// ---------------------------------------------------------------------------
#define FT_LD 72
#define BUF_HALVES (4 * 64 * FT_LD)           // Kh,Kl,Vh,Vl = 18432 halves
#define AT_SMEM_BYTES (2 * BUF_HALVES * 2)    // 73728 bytes

__global__ __launch_bounds__(256) void attn_kernel(float* __restrict__ Out)
{
    extern __shared__ char smr[];
    half_t* const buf[2] = { (half_t*)smr, (half_t*)smr + BUF_HALVES };

    const int tid = threadIdx.x;
    const int lane = tid & 31;
    const int wid = tid >> 5;
    const int r_fr = lane >> 2;
    const int c_fr = (lane & 3) * 2;
    const int mb = wid * 16;

    const int qt = blockIdx.x;          // 0..1
    const int b  = blockIdx.y;
    const int q0 = qt * 128;
    const int njt = qt * 2 + 2;
    const float scale = 0.125f;

    // --- stage Q, extract A-frags ---
    uint32_t qh[4][4], ql[4][4];
    {
        half_t* Qsh = buf[1];
        half_t* Qsl = buf[1] + 128 * FT_LD;
        const half_t* Qhg = g_Qh + (size_t)(b * SEQ + q0) * HDIM;
        const half_t* Qlg = g_Ql + (size_t)(b * SEQ + q0) * HDIM;
        for (int idx = tid; idx < 1024; idx += 256) {
            const int r = idx >> 3;
            const int q8 = (idx & 7) * 8;
            *(float4*)(Qsh + r * FT_LD + q8) = *(const float4*)(Qhg + r * HDIM + q8);
            *(float4*)(Qsl + r * FT_LD + q8) = *(const float4*)(Qlg + r * HDIM + q8);
        }
        __syncthreads();
#pragma unroll
        for (int ks = 0; ks < 4; ++ks) {
            const int kc = ks * 16 + c_fr;
            qh[ks][0] = *(const uint32_t*)(Qsh + (mb + r_fr) * FT_LD + kc);
            qh[ks][1] = *(const uint32_t*)(Qsh + (mb + r_fr + 8) * FT_LD + kc);
            qh[ks][2] = *(const uint32_t*)(Qsh + (mb + r_fr) * FT_LD + kc + 8);
            qh[ks][3] = *(const uint32_t*)(Qsh + (mb + r_fr + 8) * FT_LD + kc + 8);
            ql[ks][0] = *(const uint32_t*)(Qsl + (mb + r_fr) * FT_LD + kc);
            ql[ks][1] = *(const uint32_t*)(Qsl + (mb + r_fr + 8) * FT_LD + kc);
            ql[ks][2] = *(const uint32_t*)(Qsl + (mb + r_fr) * FT_LD + kc + 8);
            ql[ks][3] = *(const uint32_t*)(Qsl + (mb + r_fr + 8) * FT_LD + kc + 8);
        }
        __syncthreads();
    }

    float o[8][4];
#pragma unroll
    for (int nt = 0; nt < 8; ++nt)
#pragma unroll
        for (int i = 0; i < 4; ++i) o[nt][i] = 0.0f;
    float m0 = -3.4e38f, m1 = -3.4e38f, l0 = 0.0f, l1 = 0.0f;

    const half_t* Khg = g_Kh + (size_t)b * SEQ * HDIM;
    const half_t* Klg = g_Kl + (size_t)b * SEQ * HDIM;
    const half_t* Vhg = g_Vth + (size_t)b * HDIM * SEQ;
    const half_t* Vlg = g_Vtl + (size_t)b * HDIM * SEQ;

    auto load_tile = [&](int jt, half_t* dst) {
        half_t* Kh = dst;
        half_t* Kl = dst + 64 * FT_LD;
        half_t* Vh = dst + 2 * 64 * FT_LD;
        half_t* Vl = dst + 3 * 64 * FT_LD;
        const half_t* kh = Khg + (size_t)jt * 64 * HDIM;
        const half_t* kl = Klg + (size_t)jt * 64 * HDIM;
        const half_t* vh = Vhg + jt * 64;
        const half_t* vl = Vlg + jt * 64;
        for (int idx = tid; idx < 512; idx += 256) {
            const int r = idx >> 3;
            const int q8 = (idx & 7) * 8;
            *(float4*)(Kh + r * FT_LD + q8) = *(const float4*)(kh + r * HDIM + q8);
            *(float4*)(Kl + r * FT_LD + q8) = *(const float4*)(kl + r * HDIM + q8);
            *(float4*)(Vh + r * FT_LD + q8) = *(const float4*)(vh + (size_t)r * SEQ + q8);
            *(float4*)(Vl + r * FT_LD + q8) = *(const float4*)(vl + (size_t)r * SEQ + q8);
        }
    };

    load_tile(0, buf[0]);
    __syncthreads();

    // per-lane ldmatrix base offsets (within a K or V sub-tile)
    const int lds_li = lane & 7;         // row within 8x8 matrix
    const int lds_sel = lane >> 3;       // 0,1: hi (col 0,8); 2,3: lo (col 0,8)
    const uint32_t lds_off =
        (uint32_t)(((lds_sel >> 1) * (64 * FT_LD) + lds_li * FT_LD + (lds_sel & 1) * 8) * 2);

    for (int jt = 0; jt < njt; ++jt) {
        half_t* cur = buf[jt & 1];
        if (jt + 1 < njt) load_tile(jt + 1, buf[(jt + 1) & 1]);

        const bool active = (jt * 64) <= (q0 + mb + 15);
        if (active) {
            const uint32_t kbase = (uint32_t)__cvta_generic_to_shared(cur) + lds_off;
            const uint32_t vbase = kbase + (uint32_t)(2 * 64 * FT_LD * 2);

            // --- S = Q K^T ---
            float s[8][4];
#pragma unroll
            for (int nt = 0; nt < 8; ++nt)
#pragma unroll
                for (int i = 0; i < 4; ++i) s[nt][i] = 0.0f;
#pragma unroll
            for (int ks = 0; ks < 4; ++ks) {
#pragma unroll
                for (int nt = 0; nt < 8; ++nt) {
                    uint32_t bh0, bh1, bl0, bl1;
                    ldsm_x4(bh0, bh1, bl0, bl1,
                            kbase + (uint32_t)(((nt * 8) * FT_LD + ks * 16) * 2));
                    mma_bf16(s[nt], qh[ks], bh0, bh1);
                    mma_bf16(s[nt], qh[ks], bl0, bl1);
                    mma_bf16(s[nt], ql[ks], bh0, bh1);
                }
            }

            // --- scale + causal mask ---
            const int rowg0 = q0 + mb + r_fr;
            const int rowg1 = rowg0 + 8;
            const bool needm = (jt * 64 + 63) > (q0 + mb);
#pragma unroll
            for (int nt = 0; nt < 8; ++nt) {
                const int colg = jt * 64 + nt * 8 + c_fr;
                s[nt][0] *= scale; s[nt][1] *= scale;
                s[nt][2] *= scale; s[nt][3] *= scale;
                if (needm) {
                    if (colg     > rowg0) s[nt][0] = -3.4e38f;
                    if (colg + 1 > rowg0) s[nt][1] = -3.4e38f;
                    if (colg     > rowg1) s[nt][2] = -3.4e38f;
                    if (colg + 1 > rowg1) s[nt][3] = -3.4e38f;
                }
            }

            // --- online softmax ---
            float mx0 = -3.4e38f, mx1 = -3.4e38f;
#pragma unroll
            for (int nt = 0; nt < 8; ++nt) {
                mx0 = fmaxf(mx0, fmaxf(s[nt][0], s[nt][1]));
                mx1 = fmaxf(mx1, fmaxf(s[nt][2], s[nt][3]));
            }
            mx0 = fmaxf(mx0, __shfl_xor_sync(0xffffffffu, mx0, 1));
            mx0 = fmaxf(mx0, __shfl_xor_sync(0xffffffffu, mx0, 2));
            mx1 = fmaxf(mx1, __shfl_xor_sync(0xffffffffu, mx1, 1));
            mx1 = fmaxf(mx1, __shfl_xor_sync(0xffffffffu, mx1, 2));
            const float mn0 = fmaxf(m0, mx0);
            const float mn1 = fmaxf(m1, mx1);
            const float a0 = __expf(m0 - mn0);
            const float a1 = __expf(m1 - mn1);
            l0 *= a0; l1 *= a1;
#pragma unroll
            for (int nt = 0; nt < 8; ++nt) {
                o[nt][0] *= a0; o[nt][1] *= a0;
                o[nt][2] *= a1; o[nt][3] *= a1;
            }
            m0 = mn0; m1 = mn1;

            // --- P = exp(S-m) -> bf16 A-frags in regs ---
            uint32_t pa[4][4], pl[4][4];
            float sum0 = 0.0f, sum1 = 0.0f;
#pragma unroll
            for (int nt = 0; nt < 8; ++nt) {
                const float p0 = __expf(s[nt][0] - mn0);
                const float p1 = __expf(s[nt][1] - mn0);
                const float p2 = __expf(s[nt][2] - mn1);
                const float p3 = __expf(s[nt][3] - mn1);
                sum0 += p0 + p1;
                sum1 += p2 + p3;
                uint32_t h01, l01, h23, l23;
                split2(p0, p1, h01, l01);
                split2(p2, p3, h23, l23);
                const int ks = nt >> 1;
                const int off = (nt & 1) * 2;
                pa[ks][off]     = h01;
                pa[ks][off + 1] = h23;
                pl[ks][off]     = l01;
                pl[ks][off + 1] = l23;
            }
            sum0 += __shfl_xor_sync(0xffffffffu, sum0, 1);
            sum0 += __shfl_xor_sync(0xffffffffu, sum0, 2);
            sum1 += __shfl_xor_sync(0xffffffffu, sum1, 1);
            sum1 += __shfl_xor_sync(0xffffffffu, sum1, 2);
            l0 += sum0; l1 += sum1;

            // --- O += P V ---
#pragma unroll
            for (int ks = 0; ks < 4; ++ks) {
#pragma unroll
                for (int nto = 0; nto < 8; ++nto) {
                    uint32_t bh0, bh1, bl0, bl1;
                    ldsm_x4(bh0, bh1, bl0, bl1,
                            vbase + (uint32_t)(((nto * 8) * FT_LD + ks * 16) * 2));
                    mma_bf16(o[nto], pa[ks], bh0, bh1);
                    mma_bf16(o[nto], pa[ks], bl0, bl1);
                    mma_bf16(o[nto], pl[ks], bh0, bh1);
                }
            }
        }
        __syncthreads();
    }

    // --- epilogue ---
    {
        const float r0v = 1.0f / l0;
        const float r1v = 1.0f / l1;
        float* Og = Out + (size_t)(b * SEQ + q0 + mb) * HDIM;
#pragma unroll
        for (int nto = 0; nto < 8; ++nto) {
            const int col = nto * 8 + c_fr;
            float2 v0, v1;
            v0.x = o[nto][0] * r0v; v0.y = o[nto][1] * r0v;
            v1.x = o[nto][2] * r1v; v1.y = o[nto][3] * r1v;
            *(float2*)(Og + (size_t)r_fr * HDIM + col)       = v0;
            *(float2*)(Og + (size_t)(r_fr + 8) * HDIM + col) = v1;
        }
    }
}

// ---------------------------------------------------------------------------
extern "C" void kernel_launch(void* const* d_in, const int* in_sizes, int n_in,
                              void* d_out, int out_size)
{
    const float* X  = (const float*)d_in[0];   // [512,256,384]
    const float* Wk = (const float*)d_in[1];   // [384,64]
    const float* Wq = (const float*)d_in[2];   // [384,64]
    const float* Wv = (const float*)d_in[3];   // [384,64]
    float* Out = (float*)d_out;                // [512,256,64]

    (void)in_sizes; (void)n_in; (void)out_size;

    cudaFuncSetAttribute(proj_kernel,
                         cudaFuncAttributeMaxDynamicSharedMemorySize, PJ_SMEM_BYTES);
    cudaFuncSetAttribute(attn_kernel,
                         cudaFuncAttributeMaxDynamicSharedMemorySize, AT_SMEM_BYTES);

    proj_kernel<<<NROWS / 128, 256, PJ_SMEM_BYTES>>>(X, Wq, Wk, Wv);

    dim3 grid(2, BATCH);
    attn_kernel<<<grid, 256, AT_SMEM_BYTES>>>(Out);
}

// round 9
// speedup vs baseline: 1.2253x; 1.2253x over previous
#include <cuda_runtime.h>
#include <cuda_bf16.h>
#include <cstdint>

#define BATCH 512
#define SEQ   256
#define EMBED 384
#define HDIM  64
#define NROWS (BATCH * SEQ)   // 131072

typedef uint16_t half_t;

// ---------------------------------------------------------------------------
// Global scratch: projected Q/K/V in split bf16.
//   Qh/Ql, Kh/Kl: [b][s][d]   (row.col mma layout for S = Q K^T)
//   Vth/Vtl:      [b][d][s]   (B operand layout for O = P V)
// W split-bf16: [mat][n][k].
// ---------------------------------------------------------------------------
__device__ half_t g_Qh[(size_t)NROWS * HDIM];
__device__ half_t g_Ql[(size_t)NROWS * HDIM];
__device__ half_t g_Kh[(size_t)NROWS * HDIM];
__device__ half_t g_Kl[(size_t)NROWS * HDIM];
__device__ half_t g_Vth[(size_t)BATCH * HDIM * SEQ];
__device__ half_t g_Vtl[(size_t)BATCH * HDIM * SEQ];
__device__ __nv_bfloat16 g_Wh[3 * HDIM * EMBED];
__device__ __nv_bfloat16 g_Wl[3 * HDIM * EMBED];

// ---------------------------------------------------------------------------
__device__ __forceinline__ void mma_bf16(float* d, const uint32_t* a,
                                         uint32_t b0, uint32_t b1) {
    asm volatile(
        "mma.sync.aligned.m16n8k16.row.col.f32.bf16.bf16.f32 "
        "{%0,%1,%2,%3}, {%4,%5,%6,%7}, {%8,%9}, {%0,%1,%2,%3};"
        : "+f"(d[0]), "+f"(d[1]), "+f"(d[2]), "+f"(d[3])
        : "r"(a[0]), "r"(a[1]), "r"(a[2]), "r"(a[3]), "r"(b0), "r"(b1));
}

__device__ __forceinline__ void ldsm_x4(uint32_t& r0, uint32_t& r1,
                                        uint32_t& r2, uint32_t& r3,
                                        uint32_t addr) {
    asm volatile(
        "ldmatrix.sync.aligned.m8n8.x4.shared.b16 {%0,%1,%2,%3}, [%4];"
        : "=r"(r0), "=r"(r1), "=r"(r2), "=r"(r3) : "r"(addr));
}

__device__ __forceinline__ void split2(float x, float y, uint32_t& h, uint32_t& l) {
    const __nv_bfloat162 hh = __floats2bfloat162_rn(x, y);
    const __nv_bfloat162 ll = __floats2bfloat162_rn(
        x - __bfloat162float(hh.x), y - __bfloat162float(hh.y));
    h = *(const uint32_t*)&hh;
    l = *(const uint32_t*)&ll;
}

// ---------------------------------------------------------------------------
// W convert (4.5us, coalesced once) — measured better than in-proj conversion.
// ---------------------------------------------------------------------------
__global__ void wconv_kernel(const float* __restrict__ Wq,
                             const float* __restrict__ Wk,
                             const float* __restrict__ Wv)
{
    const int idx = blockIdx.x * 256 + threadIdx.x;
    const int mat = idx / (HDIM * EMBED);
    const int rem = idx % (HDIM * EMBED);
    const int n = rem / EMBED;
    const int k = rem % EMBED;
    const float* W = (mat == 0) ? Wq : ((mat == 1) ? Wk : Wv);
    const float w = W[(size_t)k * HDIM + n];
    const __nv_bfloat16 hi = __float2bfloat16(w);
    const __nv_bfloat16 lo = __float2bfloat16(w - __bfloat162float(hi));
    g_Wh[idx] = hi;
    g_Wl[idx] = lo;
}

// ---------------------------------------------------------------------------
// Projection via HMMA (R6/R7 version, measured ~205us).
// ---------------------------------------------------------------------------
#define AK_LD 72
#define OFF_AH 0
#define OFF_AL (OFF_AH + 128 * AK_LD)
#define OFF_BH (OFF_AL + 128 * AK_LD)
#define OFF_BL (OFF_BH + 192 * AK_LD)
#define MMA_SMEM_HALVES (OFF_BL + 192 * AK_LD)
#define ST_LD 196
#define PJ_SMEM_BYTES (128 * ST_LD * 4 > MMA_SMEM_HALVES * 2 ? 128 * ST_LD * 4 : MMA_SMEM_HALVES * 2)

__global__ __launch_bounds__(256) void proj_kernel(const float* __restrict__ X)
{
    extern __shared__ char smraw[];
    half_t* Ah = (half_t*)(smraw) + OFF_AH;
    half_t* Al = (half_t*)(smraw) + OFF_AL;
    half_t* Bh = (half_t*)(smraw) + OFF_BH;
    half_t* Bl = (half_t*)(smraw) + OFF_BL;
    float*  stage = (float*)smraw;

    const int tid = threadIdx.x;
    const int lane = tid & 31;
    const int wid = tid >> 5;
    const int warp_m = wid & 3;
    const int warp_n = wid >> 2;
    const int row0 = blockIdx.x * 128;

    float acc[2][12][4];
#pragma unroll
    for (int mt = 0; mt < 2; ++mt)
#pragma unroll
        for (int nt = 0; nt < 12; ++nt)
#pragma unroll
            for (int i = 0; i < 4; ++i) acc[mt][nt][i] = 0.0f;

    const int r_fr = lane >> 2;
    const int c_fr = (lane & 3) * 2;

    for (int c = 0; c < 6; ++c) {
#pragma unroll
        for (int i = 0; i < 8; ++i) {
            const int idx = i * 256 + tid;
            const int m = idx >> 4;
            const int c4 = (idx & 15) * 4;
            const float4 v = *(const float4*)(X + (size_t)(row0 + m) * EMBED + c * 64 + c4);
            uint32_t h0, l0, h1, l1;
            split2(v.x, v.y, h0, l0);
            split2(v.z, v.w, h1, l1);
            uint2 hv, lv;
            hv.x = h0; hv.y = h1; lv.x = l0; lv.y = l1;
            *(uint2*)(Ah + m * AK_LD + c4) = hv;
            *(uint2*)(Al + m * AK_LD + c4) = lv;
        }
#pragma unroll
        for (int i = 0; i < 6; ++i) {
            const int idx = i * 256 + tid;
            const int n = idx >> 3;
            const int q = idx & 7;
            const size_t gb = (size_t)n * EMBED + c * 64 + q * 8;
            *(float4*)(Bh + n * AK_LD + q * 8) = *(const float4*)((const half_t*)g_Wh + gb);
            *(float4*)(Bl + n * AK_LD + q * 8) = *(const float4*)((const half_t*)g_Wl + gb);
        }
        __syncthreads();

#pragma unroll
        for (int ks = 0; ks < 4; ++ks) {
            const int kc = ks * 16 + c_fr;
            uint32_t ah[2][4], al[2][4];
#pragma unroll
            for (int mt = 0; mt < 2; ++mt) {
                const int mb = warp_m * 32 + mt * 16;
                ah[mt][0] = *(const uint32_t*)(Ah + (mb + r_fr) * AK_LD + kc);
                ah[mt][1] = *(const uint32_t*)(Ah + (mb + r_fr + 8) * AK_LD + kc);
                ah[mt][2] = *(const uint32_t*)(Ah + (mb + r_fr) * AK_LD + kc + 8);
                ah[mt][3] = *(const uint32_t*)(Ah + (mb + r_fr + 8) * AK_LD + kc + 8);
                al[mt][0] = *(const uint32_t*)(Al + (mb + r_fr) * AK_LD + kc);
                al[mt][1] = *(const uint32_t*)(Al + (mb + r_fr + 8) * AK_LD + kc);
                al[mt][2] = *(const uint32_t*)(Al + (mb + r_fr) * AK_LD + kc + 8);
                al[mt][3] = *(const uint32_t*)(Al + (mb + r_fr + 8) * AK_LD + kc + 8);
            }
#pragma unroll
            for (int nt = 0; nt < 12; ++nt) {
                const int nb = warp_n * 96 + nt * 8 + r_fr;
                const uint32_t bh0 = *(const uint32_t*)(Bh + nb * AK_LD + kc);
                const uint32_t bh1 = *(const uint32_t*)(Bh + nb * AK_LD + kc + 8);
                const uint32_t bl0 = *(const uint32_t*)(Bl + nb * AK_LD + kc);
                const uint32_t bl1 = *(const uint32_t*)(Bl + nb * AK_LD + kc + 8);
                mma_bf16(acc[0][nt], ah[0], bh0, bh1);
                mma_bf16(acc[1][nt], ah[1], bh0, bh1);
                mma_bf16(acc[0][nt], ah[0], bl0, bl1);
                mma_bf16(acc[1][nt], ah[1], bl0, bl1);
                mma_bf16(acc[0][nt], al[0], bh0, bh1);
                mma_bf16(acc[1][nt], al[1], bh0, bh1);
            }
        }
        __syncthreads();
    }

#pragma unroll
    for (int mt = 0; mt < 2; ++mt) {
        const int r0 = warp_m * 32 + mt * 16 + r_fr;
#pragma unroll
        for (int nt = 0; nt < 12; ++nt) {
            const int col = warp_n * 96 + nt * 8 + c_fr;
            float2 v0, v1;
            v0.x = acc[mt][nt][0]; v0.y = acc[mt][nt][1];
            v1.x = acc[mt][nt][2]; v1.y = acc[mt][nt][3];
            *(float2*)(stage + r0 * ST_LD + col)       = v0;
            *(float2*)(stage + (r0 + 8) * ST_LD + col) = v1;
        }
    }
    __syncthreads();

    const int b = row0 >> 8;
    const int sbase = row0 & 255;

    for (int idx = tid; idx < 2048; idx += 256) {
        const int m = idx >> 4;
        const int q = (idx & 15) * 4;
        const size_t go = (size_t)(row0 + m) * HDIM + q;
        {
            const float4 v = *(const float4*)(stage + m * ST_LD + q);
            uint32_t h0, l0, h1, l1;
            split2(v.x, v.y, h0, l0);
            split2(v.z, v.w, h1, l1);
            uint2 hv, lv; hv.x = h0; hv.y = h1; lv.x = l0; lv.y = l1;
            *(uint2*)(g_Qh + go) = hv;
            *(uint2*)(g_Ql + go) = lv;
        }
        {
            const float4 v = *(const float4*)(stage + m * ST_LD + 64 + q);
            uint32_t h0, l0, h1, l1;
            split2(v.x, v.y, h0, l0);
            split2(v.z, v.w, h1, l1);
            uint2 hv, lv; hv.x = h0; hv.y = h1; lv.x = l0; lv.y = l1;
            *(uint2*)(g_Kh + go) = hv;
            *(uint2*)(g_Kl + go) = lv;
        }
    }
    for (int idx = tid; idx < 2048; idx += 256) {
        const int d = idx >> 5;
        const int s0 = (idx & 31) * 4;
        float v0 = stage[(s0 + 0) * ST_LD + 128 + d];
        float v1 = stage[(s0 + 1) * ST_LD + 128 + d];
        float v2 = stage[(s0 + 2) * ST_LD + 128 + d];
        float v3 = stage[(s0 + 3) * ST_LD + 128 + d];
        uint32_t h0, l0, h1, l1;
        split2(v0, v1, h0, l0);
        split2(v2, v3, h1, l1);
        uint2 hv, lv; hv.x = h0; hv.y = h1; lv.x = l0; lv.y = l1;
        const size_t go = ((size_t)b * HDIM + d) * SEQ + sbase + s0;
        *(uint2*)(g_Vth + go) = hv;
        *(uint2*)(g_Vtl + go) = lv;
    }
}

// ---------------------------------------------------------------------------
// FlashAttention-2 attention. Grid (2, 512), 2 CTAs/SM target.
// Q lives in a dedicated smem region; Q A-frags re-loaded per tile via
// ldmatrix (frees 32 regs -> fits 128-reg budget for occupancy 2).
// ---------------------------------------------------------------------------
#define FT_LD 72
#define QS_HALVES (2 * 128 * FT_LD)           // Qh+Ql = 18432 halves (36 KB)
#define BUF_HALVES (4 * 64 * FT_LD)           // Kh,Kl,Vh,Vl = 18432 halves
#define AT_SMEM_BYTES ((QS_HALVES + 2 * BUF_HALVES) * 2)   // 110592 bytes

__global__ __launch_bounds__(256, 2) void attn_kernel(float* __restrict__ Out)
{
    extern __shared__ char smr[];
    half_t* Qsh = (half_t*)smr;                       // [128][FT_LD] hi
    half_t* Qsl = Qsh + 128 * FT_LD;                  // lo
    half_t* const buf[2] = { (half_t*)smr + QS_HALVES,
                             (half_t*)smr + QS_HALVES + BUF_HALVES };

    const int tid = threadIdx.x;
    const int lane = tid & 31;
    const int wid = tid >> 5;
    const int r_fr = lane >> 2;
    const int c_fr = (lane & 3) * 2;
    const int mb = wid * 16;

    const int qt = blockIdx.x;          // 0..1
    const int b  = blockIdx.y;
    const int q0 = qt * 128;
    const int njt = qt * 2 + 2;
    const float scale = 0.125f;

    // --- stage Q (persistent in smem) ---
    {
        const half_t* Qhg = g_Qh + (size_t)(b * SEQ + q0) * HDIM;
        const half_t* Qlg = g_Ql + (size_t)(b * SEQ + q0) * HDIM;
        for (int idx = tid; idx < 1024; idx += 256) {
            const int r = idx >> 3;
            const int q8 = (idx & 7) * 8;
            *(float4*)(Qsh + r * FT_LD + q8) = *(const float4*)(Qhg + r * HDIM + q8);
            *(float4*)(Qsl + r * FT_LD + q8) = *(const float4*)(Qlg + r * HDIM + q8);
        }
    }

    float o[8][4];
#pragma unroll
    for (int nt = 0; nt < 8; ++nt)
#pragma unroll
        for (int i = 0; i < 4; ++i) o[nt][i] = 0.0f;
    float m0 = -3.4e38f, m1 = -3.4e38f, l0 = 0.0f, l1 = 0.0f;

    const half_t* Khg = g_Kh + (size_t)b * SEQ * HDIM;
    const half_t* Klg = g_Kl + (size_t)b * SEQ * HDIM;
    const half_t* Vhg = g_Vth + (size_t)b * HDIM * SEQ;
    const half_t* Vlg = g_Vtl + (size_t)b * HDIM * SEQ;

    auto load_tile = [&](int jt, half_t* dst) {
        half_t* Kh = dst;
        half_t* Kl = dst + 64 * FT_LD;
        half_t* Vh = dst + 2 * 64 * FT_LD;
        half_t* Vl = dst + 3 * 64 * FT_LD;
        const half_t* kh = Khg + (size_t)jt * 64 * HDIM;
        const half_t* kl = Klg + (size_t)jt * 64 * HDIM;
        const half_t* vh = Vhg + jt * 64;
        const half_t* vl = Vlg + jt * 64;
        for (int idx = tid; idx < 512; idx += 256) {
            const int r = idx >> 3;
            const int q8 = (idx & 7) * 8;
            *(float4*)(Kh + r * FT_LD + q8) = *(const float4*)(kh + r * HDIM + q8);
            *(float4*)(Kl + r * FT_LD + q8) = *(const float4*)(kl + r * HDIM + q8);
            *(float4*)(Vh + r * FT_LD + q8) = *(const float4*)(vh + (size_t)r * SEQ + q8);
            *(float4*)(Vl + r * FT_LD + q8) = *(const float4*)(vl + (size_t)r * SEQ + q8);
        }
    };

    load_tile(0, buf[0]);
    __syncthreads();

    // --- per-lane ldmatrix offsets ---
    // B-frags (K/V): 4 matrices = {hi col0, hi col8, lo col0, lo col8}
    const int bli = lane & 7;
    const int bsel = lane >> 3;
    const uint32_t b_off =
        (uint32_t)(((bsel >> 1) * (64 * FT_LD) + bli * FT_LD + (bsel & 1) * 8) * 2);
    // A-frags (Q): 4 matrices = {rows mb col0, rows mb+8 col0, rows mb col8, rows mb+8 col8}
    const uint32_t qa_off =
        (uint32_t)(((mb + (bsel & 1) * 8 + bli) * FT_LD + (bsel >> 1) * 8) * 2);
    const uint32_t qsh_base = (uint32_t)__cvta_generic_to_shared(Qsh) + qa_off;
    const uint32_t qsl_base = qsh_base + (uint32_t)(128 * FT_LD * 2);

    for (int jt = 0; jt < njt; ++jt) {
        half_t* cur = buf[jt & 1];
        if (jt + 1 < njt) load_tile(jt + 1, buf[(jt + 1) & 1]);

        const bool active = (jt * 64) <= (q0 + mb + 15);
        if (active) {
            const uint32_t kbase = (uint32_t)__cvta_generic_to_shared(cur) + b_off;
            const uint32_t vbase = kbase + (uint32_t)(2 * 64 * FT_LD * 2);

            // --- S = Q K^T ---
            float s[8][4];
#pragma unroll
            for (int nt = 0; nt < 8; ++nt)
#pragma unroll
                for (int i = 0; i < 4; ++i) s[nt][i] = 0.0f;
#pragma unroll
            for (int ks = 0; ks < 4; ++ks) {
                uint32_t qh[4], ql[4];
                ldsm_x4(qh[0], qh[1], qh[2], qh[3], qsh_base + (uint32_t)(ks * 32));
                ldsm_x4(ql[0], ql[1], ql[2], ql[3], qsl_base + (uint32_t)(ks * 32));
#pragma unroll
                for (int nt = 0; nt < 8; ++nt) {
                    uint32_t bh0, bh1, bl0, bl1;
                    ldsm_x4(bh0, bh1, bl0, bl1,
                            kbase + (uint32_t)(((nt * 8) * FT_LD + ks * 16) * 2));
                    mma_bf16(s[nt], qh, bh0, bh1);
                    mma_bf16(s[nt], qh, bl0, bl1);
                    mma_bf16(s[nt], ql, bh0, bh1);
                }
            }

            // --- scale + causal mask ---
            const int rowg0 = q0 + mb + r_fr;
            const int rowg1 = rowg0 + 8;
            const bool needm = (jt * 64 + 63) > (q0 + mb);
#pragma unroll
            for (int nt = 0; nt < 8; ++nt) {
                const int colg = jt * 64 + nt * 8 + c_fr;
                s[nt][0] *= scale; s[nt][1] *= scale;
                s[nt][2] *= scale; s[nt][3] *= scale;
                if (needm) {
                    if (colg     > rowg0) s[nt][0] = -3.4e38f;
                    if (colg + 1 > rowg0) s[nt][1] = -3.4e38f;
                    if (colg     > rowg1) s[nt][2] = -3.4e38f;
                    if (colg + 1 > rowg1) s[nt][3] = -3.4e38f;
                }
            }

            // --- online softmax ---
            float mx0 = -3.4e38f, mx1 = -3.4e38f;
#pragma unroll
            for (int nt = 0; nt < 8; ++nt) {
                mx0 = fmaxf(mx0, fmaxf(s[nt][0], s[nt][1]));
                mx1 = fmaxf(mx1, fmaxf(s[nt][2], s[nt][3]));
            }
            mx0 = fmaxf(mx0, __shfl_xor_sync(0xffffffffu, mx0, 1));
            mx0 = fmaxf(mx0, __shfl_xor_sync(0xffffffffu, mx0, 2));
            mx1 = fmaxf(mx1, __shfl_xor_sync(0xffffffffu, mx1, 1));
            mx1 = fmaxf(mx1, __shfl_xor_sync(0xffffffffu, mx1, 2));
            const float mn0 = fmaxf(m0, mx0);
            const float mn1 = fmaxf(m1, mx1);
            const float a0 = __expf(m0 - mn0);
            const float a1 = __expf(m1 - mn1);
            l0 *= a0; l1 *= a1;
#pragma unroll
            for (int nt = 0; nt < 8; ++nt) {
                o[nt][0] *= a0; o[nt][1] *= a0;
                o[nt][2] *= a1; o[nt][3] *= a1;
            }
            m0 = mn0; m1 = mn1;

            // --- P = exp(S-m) -> bf16 A-frags in regs ---
            uint32_t pa[4][4], pl[4][4];
            float sum0 = 0.0f, sum1 = 0.0f;
#pragma unroll
            for (int nt = 0; nt < 8; ++nt) {
                const float p0 = __expf(s[nt][0] - mn0);
                const float p1 = __expf(s[nt][1] - mn0);
                const float p2 = __expf(s[nt][2] - mn1);
                const float p3 = __expf(s[nt][3] - mn1);
                sum0 += p0 + p1;
                sum1 += p2 + p3;
                uint32_t h01, l01, h23, l23;
                split2(p0, p1, h01, l01);
                split2(p2, p3, h23, l23);
                const int ks = nt >> 1;
                const int off = (nt & 1) * 2;
                pa[ks][off]     = h01;
                pa[ks][off + 1] = h23;
                pl[ks][off]     = l01;
                pl[ks][off + 1] = l23;
            }
            sum0 += __shfl_xor_sync(0xffffffffu, sum0, 1);
            sum0 += __shfl_xor_sync(0xffffffffu, sum0, 2);
            sum1 += __shfl_xor_sync(0xffffffffu, sum1, 1);
            sum1 += __shfl_xor_sync(0xffffffffu, sum1, 2);
            l0 += sum0; l1 += sum1;

            // --- O += P V ---
#pragma unroll
            for (int ks = 0; ks < 4; ++ks) {
#pragma unroll
                for (int nto = 0; nto < 8; ++nto) {
                    uint32_t bh0, bh1, bl0, bl1;
                    ldsm_x4(bh0, bh1, bl0, bl1,
                            vbase + (uint32_t)(((nto * 8) * FT_LD + ks * 16) * 2));
                    mma_bf16(o[nto], pa[ks], bh0, bh1);
                    mma_bf16(o[nto], pa[ks], bl0, bl1);
                    mma_bf16(o[nto], pl[ks], bh0, bh1);
                }
            }
        }
        __syncthreads();
    }

    // --- epilogue ---
    {
        const float r0v = 1.0f / l0;
        const float r1v = 1.0f / l1;
        float* Og = Out + (size_t)(b * SEQ + q0 + mb) * HDIM;
#pragma unroll
        for (int nto = 0; nto < 8; ++nto) {
            const int col = nto * 8 + c_fr;
            float2 v0, v1;
            v0.x = o[nto][0] * r0v; v0.y = o[nto][1] * r0v;
            v1.x = o[nto][2] * r1v; v1.y = o[nto][3] * r1v;
            *(float2*)(Og + (size_t)r_fr * HDIM + col)       = v0;
            *(float2*)(Og + (size_t)(r_fr + 8) * HDIM + col) = v1;
        }
    }
}

// ---------------------------------------------------------------------------
extern "C" void kernel_launch(void* const* d_in, const int* in_sizes, int n_in,
                              void* d_out, int out_size)
{
    const float* X  = (const float*)d_in[0];   // [512,256,384]
    const float* Wk = (const float*)d_in[1];   // [384,64]
    const float* Wq = (const float*)d_in[2];   // [384,64]
    const float* Wv = (const float*)d_in[3];   // [384,64]
    float* Out = (float*)d_out;                // [512,256,64]

    (void)in_sizes; (void)n_in; (void)out_size;

    cudaFuncSetAttribute(proj_kernel,
                         cudaFuncAttributeMaxDynamicSharedMemorySize, PJ_SMEM_BYTES);
    cudaFuncSetAttribute(attn_kernel,
                         cudaFuncAttributeMaxDynamicSharedMemorySize, AT_SMEM_BYTES);

    wconv_kernel<<<288, 256>>>(Wq, Wk, Wv);
    proj_kernel<<<NROWS / 128, 256, PJ_SMEM_BYTES>>>(X);

    dim3 grid(2, BATCH);
    attn_kernel<<<grid, 256, AT_SMEM_BYTES>>>(Out);
}

// round 10
// speedup vs baseline: 1.3294x; 1.0849x over previous
#include <cuda_runtime.h>
#include <cuda_bf16.h>
#include <cstdint>

#define BATCH 512
#define SEQ   256
#define EMBED 384
#define HDIM  64
#define NROWS (BATCH * SEQ)   // 131072

typedef uint16_t half_t;

// ---------------------------------------------------------------------------
// Global scratch: projected Q/K/V in split bf16.
// ---------------------------------------------------------------------------
__device__ half_t g_Qh[(size_t)NROWS * HDIM];
__device__ half_t g_Ql[(size_t)NROWS * HDIM];
__device__ half_t g_Kh[(size_t)NROWS * HDIM];
__device__ half_t g_Kl[(size_t)NROWS * HDIM];
__device__ half_t g_Vth[(size_t)BATCH * HDIM * SEQ];
__device__ half_t g_Vtl[(size_t)BATCH * HDIM * SEQ];
__device__ __nv_bfloat16 g_Wh[3 * HDIM * EMBED];
__device__ __nv_bfloat16 g_Wl[3 * HDIM * EMBED];

// ---------------------------------------------------------------------------
__device__ __forceinline__ void mma_bf16(float* d, const uint32_t* a,
                                         uint32_t b0, uint32_t b1) {
    asm volatile(
        "mma.sync.aligned.m16n8k16.row.col.f32.bf16.bf16.f32 "
        "{%0,%1,%2,%3}, {%4,%5,%6,%7}, {%8,%9}, {%0,%1,%2,%3};"
        : "+f"(d[0]), "+f"(d[1]), "+f"(d[2]), "+f"(d[3])
        : "r"(a[0]), "r"(a[1]), "r"(a[2]), "r"(a[3]), "r"(b0), "r"(b1));
}

__device__ __forceinline__ void ldsm_x4(uint32_t& r0, uint32_t& r1,
                                        uint32_t& r2, uint32_t& r3,
                                        uint32_t addr) {
    asm volatile(
        "ldmatrix.sync.aligned.m8n8.x4.shared.b16 {%0,%1,%2,%3}, [%4];"
        : "=r"(r0), "=r"(r1), "=r"(r2), "=r"(r3) : "r"(addr));
}

__device__ __forceinline__ void split2(float x, float y, uint32_t& h, uint32_t& l) {
    const __nv_bfloat162 hh = __floats2bfloat162_rn(x, y);
    const __nv_bfloat162 ll = __floats2bfloat162_rn(
        x - __bfloat162float(hh.x), y - __bfloat162float(hh.y));
    h = *(const uint32_t*)&hh;
    l = *(const uint32_t*)&ll;
}

// ---------------------------------------------------------------------------
// W convert (coalesced, once)
// ---------------------------------------------------------------------------
__global__ void wconv_kernel(const float* __restrict__ Wq,
                             const float* __restrict__ Wk,
                             const float* __restrict__ Wv)
{
    const int idx = blockIdx.x * 256 + threadIdx.x;
    const int mat = idx / (HDIM * EMBED);
    const int rem = idx % (HDIM * EMBED);
    const int n = rem / EMBED;
    const int k = rem % EMBED;
    const float* W = (mat == 0) ? Wq : ((mat == 1) ? Wk : Wv);
    const float w = W[(size_t)k * HDIM + n];
    const __nv_bfloat16 hi = __float2bfloat16(w);
    const __nv_bfloat16 lo = __float2bfloat16(w - __bfloat162float(hi));
    g_Wh[idx] = hi;
    g_Wl[idx] = lo;
}

// ---------------------------------------------------------------------------
// Projection via HMMA, double-buffered k-chunks + ldmatrix fragments.
// Per CTA: M=128, N=192 (Q|K|V), K=384 in 6 chunks of 64.
// ---------------------------------------------------------------------------
#define AK_LD 72
#define OFF_AH 0
#define OFF_AL (128 * AK_LD)
#define OFF_BH (2 * 128 * AK_LD)
#define OFF_BL (OFF_BH + 192 * AK_LD)
#define CH_HALVES (OFF_BL + 192 * AK_LD)       // 46080 halves per buffer
#define ST_LD 196
#define PJ_SMEM_BYTES (2 * CH_HALVES * 2)      // 184320 bytes (stage fits inside)

__global__ __launch_bounds__(256) void proj_kernel(const float* __restrict__ X)
{
    extern __shared__ char smraw[];
    float* stage = (float*)smraw;
    const uint32_t smb = (uint32_t)__cvta_generic_to_shared(smraw);

    const int tid = threadIdx.x;
    const int lane = tid & 31;
    const int wid = tid >> 5;
    const int warp_m = wid & 3;
    const int warp_n = wid >> 2;
    const int row0 = blockIdx.x * 128;

    const int r_fr = lane >> 2;
    const int c_fr = (lane & 3) * 2;
    const int bli = lane & 7;
    const int bsel = lane >> 3;
    // ldmatrix lane offsets (bytes)
    const uint32_t a_lane =
        (uint32_t)((((bsel & 1) * 8 + bli) * AK_LD + (bsel >> 1) * 8) * 2);
    const uint32_t b_lane =
        (uint32_t)(((bsel >> 1) * (192 * AK_LD) + bli * AK_LD + (bsel & 1) * 8) * 2);

    float acc[2][12][4];
#pragma unroll
    for (int mt = 0; mt < 2; ++mt)
#pragma unroll
        for (int nt = 0; nt < 12; ++nt)
#pragma unroll
            for (int i = 0; i < 4; ++i) acc[mt][nt][i] = 0.0f;

    // --- loaders ---
    auto ldg_x = [&](int c, float4* xr) {
#pragma unroll
        for (int i = 0; i < 8; ++i) {
            const int idx = i * 256 + tid;
            const int m = idx >> 4;
            const int c4 = (idx & 15) * 4;
            xr[i] = *(const float4*)(X + (size_t)(row0 + m) * EMBED + c * 64 + c4);
        }
    };
    auto sts_x = [&](const float4* xr, int part) {
        half_t* Ah = (half_t*)smraw + part * CH_HALVES + OFF_AH;
        half_t* Al = (half_t*)smraw + part * CH_HALVES + OFF_AL;
#pragma unroll
        for (int i = 0; i < 8; ++i) {
            const int idx = i * 256 + tid;
            const int m = idx >> 4;
            const int c4 = (idx & 15) * 4;
            uint32_t h0, l0, h1, l1;
            split2(xr[i].x, xr[i].y, h0, l0);
            split2(xr[i].z, xr[i].w, h1, l1);
            uint2 hv, lv;
            hv.x = h0; hv.y = h1; lv.x = l0; lv.y = l1;
            *(uint2*)(Ah + m * AK_LD + c4) = hv;
            *(uint2*)(Al + m * AK_LD + c4) = lv;
        }
    };
    auto ldg_sts_w = [&](int c, int part) {
        half_t* Bh = (half_t*)smraw + part * CH_HALVES + OFF_BH;
        half_t* Bl = (half_t*)smraw + part * CH_HALVES + OFF_BL;
#pragma unroll
        for (int i = 0; i < 6; ++i) {
            const int idx = i * 256 + tid;
            const int n = idx >> 3;
            const int q = idx & 7;
            const size_t gb = (size_t)n * EMBED + c * 64 + q * 8;
            *(float4*)(Bh + n * AK_LD + q * 8) = *(const float4*)((const half_t*)g_Wh + gb);
            *(float4*)(Bl + n * AK_LD + q * 8) = *(const float4*)((const half_t*)g_Wl + gb);
        }
    };

    // --- prologue: chunk 0 ---
    {
        float4 xr[8];
        ldg_x(0, xr);
        sts_x(xr, 0);
        ldg_sts_w(0, 0);
    }
    __syncthreads();

    for (int c = 0; c < 6; ++c) {
        const int p = c & 1;
        const bool pf = (c < 5);
        float4 xr[8];
        if (pf) ldg_x(c + 1, xr);          // LDG latency hides under mma below

        const uint32_t base = smb + (uint32_t)(p * CH_HALVES * 2);
        const uint32_t aB = base + a_lane;
        const uint32_t bB = base + (uint32_t)(OFF_BH * 2) + b_lane;

#pragma unroll
        for (int ks = 0; ks < 4; ++ks) {
            const uint32_t kso = (uint32_t)(ks * 32);
            uint32_t ah0[4], ah1[4], al0[4], al1[4];
            ldsm_x4(ah0[0], ah0[1], ah0[2], ah0[3],
                    aB + (uint32_t)((warp_m * 32) * AK_LD * 2) + kso);
            ldsm_x4(ah1[0], ah1[1], ah1[2], ah1[3],
                    aB + (uint32_t)((warp_m * 32 + 16) * AK_LD * 2) + kso);
            ldsm_x4(al0[0], al0[1], al0[2], al0[3],
                    aB + (uint32_t)(OFF_AL * 2) + (uint32_t)((warp_m * 32) * AK_LD * 2) + kso);
            ldsm_x4(al1[0], al1[1], al1[2], al1[3],
                    aB + (uint32_t)(OFF_AL * 2) + (uint32_t)((warp_m * 32 + 16) * AK_LD * 2) + kso);
#pragma unroll
            for (int nt = 0; nt < 12; ++nt) {
                uint32_t bh0, bh1, bl0, bl1;
                ldsm_x4(bh0, bh1, bl0, bl1,
                        bB + (uint32_t)(((warp_n * 96 + nt * 8) * AK_LD) * 2) + kso);
                mma_bf16(acc[0][nt], ah0, bh0, bh1);
                mma_bf16(acc[1][nt], ah1, bh0, bh1);
                mma_bf16(acc[0][nt], ah0, bl0, bl1);
                mma_bf16(acc[1][nt], ah1, bl0, bl1);
                mma_bf16(acc[0][nt], al0, bh0, bh1);
                mma_bf16(acc[1][nt], al1, bh0, bh1);
            }
        }

        if (pf) {
            sts_x(xr, 1 - p);
            ldg_sts_w(c + 1, 1 - p);
        }
        __syncthreads();
    }

    // --- stage accumulators to smem: stage[m][fused_col] ---
#pragma unroll
    for (int mt = 0; mt < 2; ++mt) {
        const int r0 = warp_m * 32 + mt * 16 + r_fr;
#pragma unroll
        for (int nt = 0; nt < 12; ++nt) {
            const int col = warp_n * 96 + nt * 8 + c_fr;
            float2 v0, v1;
            v0.x = acc[mt][nt][0]; v0.y = acc[mt][nt][1];
            v1.x = acc[mt][nt][2]; v1.y = acc[mt][nt][3];
            *(float2*)(stage + r0 * ST_LD + col)       = v0;
            *(float2*)(stage + (r0 + 8) * ST_LD + col) = v1;
        }
    }
    __syncthreads();

    const int b = row0 >> 8;
    const int sbase = row0 & 255;

    // --- Q / K: split bf16 [b][s][d] ---
    for (int idx = tid; idx < 2048; idx += 256) {
        const int m = idx >> 4;
        const int q = (idx & 15) * 4;
        const size_t go = (size_t)(row0 + m) * HDIM + q;
        {
            const float4 v = *(const float4*)(stage + m * ST_LD + q);
            uint32_t h0, l0, h1, l1;
            split2(v.x, v.y, h0, l0);
            split2(v.z, v.w, h1, l1);
            uint2 hv, lv; hv.x = h0; hv.y = h1; lv.x = l0; lv.y = l1;
            *(uint2*)(g_Qh + go) = hv;
            *(uint2*)(g_Ql + go) = lv;
        }
        {
            const float4 v = *(const float4*)(stage + m * ST_LD + 64 + q);
            uint32_t h0, l0, h1, l1;
            split2(v.x, v.y, h0, l0);
            split2(v.z, v.w, h1, l1);
            uint2 hv, lv; hv.x = h0; hv.y = h1; lv.x = l0; lv.y = l1;
            *(uint2*)(g_Kh + go) = hv;
            *(uint2*)(g_Kl + go) = lv;
        }
    }
    // --- V: split bf16 transposed [b][d][s] ---
    for (int idx = tid; idx < 2048; idx += 256) {
        const int d = idx >> 5;
        const int s0 = (idx & 31) * 4;
        float v0 = stage[(s0 + 0) * ST_LD + 128 + d];
        float v1 = stage[(s0 + 1) * ST_LD + 128 + d];
        float v2 = stage[(s0 + 2) * ST_LD + 128 + d];
        float v3 = stage[(s0 + 3) * ST_LD + 128 + d];
        uint32_t h0, l0, h1, l1;
        split2(v0, v1, h0, l0);
        split2(v2, v3, h1, l1);
        uint2 hv, lv; hv.x = h0; hv.y = h1; lv.x = l0; lv.y = l1;
        const size_t go = ((size_t)b * HDIM + d) * SEQ + sbase + s0;
        *(uint2*)(g_Vth + go) = hv;
        *(uint2*)(g_Vtl + go) = lv;
    }
}

// ---------------------------------------------------------------------------
// FlashAttention-2 attention — R8 version (measured 155us).
// Q A-frags resident in registers; K/V B-frags via ldmatrix.x4.
// ---------------------------------------------------------------------------
#define FT_LD 72
#define BUF_HALVES (4 * 64 * FT_LD)           // Kh,Kl,Vh,Vl = 18432 halves
#define AT_SMEM_BYTES (2 * BUF_HALVES * 2)    // 73728 bytes

__global__ __launch_bounds__(256) void attn_kernel(float* __restrict__ Out)
{
    extern __shared__ char smr[];
    half_t* const buf[2] = { (half_t*)smr, (half_t*)smr + BUF_HALVES };

    const int tid = threadIdx.x;
    const int lane = tid & 31;
    const int wid = tid >> 5;
    const int r_fr = lane >> 2;
    const int c_fr = (lane & 3) * 2;
    const int mb = wid * 16;

    const int qt = blockIdx.x;          // 0..1
    const int b  = blockIdx.y;
    const int q0 = qt * 128;
    const int njt = qt * 2 + 2;
    const float scale = 0.125f;

    // --- stage Q, extract A-frags into registers ---
    uint32_t qh[4][4], ql[4][4];
    {
        half_t* Qsh = buf[1];
        half_t* Qsl = buf[1] + 128 * FT_LD;
        const half_t* Qhg = g_Qh + (size_t)(b * SEQ + q0) * HDIM;
        const half_t* Qlg = g_Ql + (size_t)(b * SEQ + q0) * HDIM;
        for (int idx = tid; idx < 1024; idx += 256) {
            const int r = idx >> 3;
            const int q8 = (idx & 7) * 8;
            *(float4*)(Qsh + r * FT_LD + q8) = *(const float4*)(Qhg + r * HDIM + q8);
            *(float4*)(Qsl + r * FT_LD + q8) = *(const float4*)(Qlg + r * HDIM + q8);
        }
        __syncthreads();
#pragma unroll
        for (int ks = 0; ks < 4; ++ks) {
            const int kc = ks * 16 + c_fr;
            qh[ks][0] = *(const uint32_t*)(Qsh + (mb + r_fr) * FT_LD + kc);
            qh[ks][1] = *(const uint32_t*)(Qsh + (mb + r_fr + 8) * FT_LD + kc);
            qh[ks][2] = *(const uint32_t*)(Qsh + (mb + r_fr) * FT_LD + kc + 8);
            qh[ks][3] = *(const uint32_t*)(Qsh + (mb + r_fr + 8) * FT_LD + kc + 8);
            ql[ks][0] = *(const uint32_t*)(Qsl + (mb + r_fr) * FT_LD + kc);
            ql[ks][1] = *(const uint32_t*)(Qsl + (mb + r_fr + 8) * FT_LD + kc);
            ql[ks][2] = *(const uint32_t*)(Qsl + (mb + r_fr) * FT_LD + kc + 8);
            ql[ks][3] = *(const uint32_t*)(Qsl + (mb + r_fr + 8) * FT_LD + kc + 8);
        }
        __syncthreads();
    }

    float o[8][4];
#pragma unroll
    for (int nt = 0; nt < 8; ++nt)
#pragma unroll
        for (int i = 0; i < 4; ++i) o[nt][i] = 0.0f;
    float m0 = -3.4e38f, m1 = -3.4e38f, l0 = 0.0f, l1 = 0.0f;

    const half_t* Khg = g_Kh + (size_t)b * SEQ * HDIM;
    const half_t* Klg = g_Kl + (size_t)b * SEQ * HDIM;
    const half_t* Vhg = g_Vth + (size_t)b * HDIM * SEQ;
    const half_t* Vlg = g_Vtl + (size_t)b * HDIM * SEQ;

    auto load_tile = [&](int jt, half_t* dst) {
        half_t* Kh = dst;
        half_t* Kl = dst + 64 * FT_LD;
        half_t* Vh = dst + 2 * 64 * FT_LD;
        half_t* Vl = dst + 3 * 64 * FT_LD;
        const half_t* kh = Khg + (size_t)jt * 64 * HDIM;
        const half_t* kl = Klg + (size_t)jt * 64 * HDIM;
        const half_t* vh = Vhg + jt * 64;
        const half_t* vl = Vlg + jt * 64;
        for (int idx = tid; idx < 512; idx += 256) {
            const int r = idx >> 3;
            const int q8 = (idx & 7) * 8;
            *(float4*)(Kh + r * FT_LD + q8) = *(const float4*)(kh + r * HDIM + q8);
            *(float4*)(Kl + r * FT_LD + q8) = *(const float4*)(kl + r * HDIM + q8);
            *(float4*)(Vh + r * FT_LD + q8) = *(const float4*)(vh + (size_t)r * SEQ + q8);
            *(float4*)(Vl + r * FT_LD + q8) = *(const float4*)(vl + (size_t)r * SEQ + q8);
        }
    };

    load_tile(0, buf[0]);
    __syncthreads();

    const int lds_li = lane & 7;
    const int lds_sel = lane >> 3;
    const uint32_t lds_off =
        (uint32_t)(((lds_sel >> 1) * (64 * FT_LD) + lds_li * FT_LD + (lds_sel & 1) * 8) * 2);

    for (int jt = 0; jt < njt; ++jt) {
        half_t* cur = buf[jt & 1];
        if (jt + 1 < njt) load_tile(jt + 1, buf[(jt + 1) & 1]);

        const bool active = (jt * 64) <= (q0 + mb + 15);
        if (active) {
            const uint32_t kbase = (uint32_t)__cvta_generic_to_shared(cur) + lds_off;
            const uint32_t vbase = kbase + (uint32_t)(2 * 64 * FT_LD * 2);

            float s[8][4];
#pragma unroll
            for (int nt = 0; nt < 8; ++nt)
#pragma unroll
                for (int i = 0; i < 4; ++i) s[nt][i] = 0.0f;
#pragma unroll
            for (int ks = 0; ks < 4; ++ks) {
#pragma unroll
                for (int nt = 0; nt < 8; ++nt) {
                    uint32_t bh0, bh1, bl0, bl1;
                    ldsm_x4(bh0, bh1, bl0, bl1,
                            kbase + (uint32_t)(((nt * 8) * FT_LD + ks * 16) * 2));
                    mma_bf16(s[nt], qh[ks], bh0, bh1);
                    mma_bf16(s[nt], qh[ks], bl0, bl1);
                    mma_bf16(s[nt], ql[ks], bh0, bh1);
                }
            }

            const int rowg0 = q0 + mb + r_fr;
            const int rowg1 = rowg0 + 8;
            const bool needm = (jt * 64 + 63) > (q0 + mb);
#pragma unroll
            for (int nt = 0; nt < 8; ++nt) {
                const int colg = jt * 64 + nt * 8 + c_fr;
                s[nt][0] *= scale; s[nt][1] *= scale;
                s[nt][2] *= scale; s[nt][3] *= scale;
                if (needm) {
                    if (colg     > rowg0) s[nt][0] = -3.4e38f;
                    if (colg + 1 > rowg0) s[nt][1] = -3.4e38f;
                    if (colg     > rowg1) s[nt][2] = -3.4e38f;
                    if (colg + 1 > rowg1) s[nt][3] = -3.4e38f;
                }
            }

            float mx0 = -3.4e38f, mx1 = -3.4e38f;
#pragma unroll
            for (int nt = 0; nt < 8; ++nt) {
                mx0 = fmaxf(mx0, fmaxf(s[nt][0], s[nt][1]));
                mx1 = fmaxf(mx1, fmaxf(s[nt][2], s[nt][3]));
            }
            mx0 = fmaxf(mx0, __shfl_xor_sync(0xffffffffu, mx0, 1));
            mx0 = fmaxf(mx0, __shfl_xor_sync(0xffffffffu, mx0, 2));
            mx1 = fmaxf(mx1, __shfl_xor_sync(0xffffffffu, mx1, 1));
            mx1 = fmaxf(mx1, __shfl_xor_sync(0xffffffffu, mx1, 2));
            const float mn0 = fmaxf(m0, mx0);
            const float mn1 = fmaxf(m1, mx1);
            const float a0 = __expf(m0 - mn0);
            const float a1 = __expf(m1 - mn1);
            l0 *= a0; l1 *= a1;
#pragma unroll
            for (int nt = 0; nt < 8; ++nt) {
                o[nt][0] *= a0; o[nt][1] *= a0;
                o[nt][2] *= a1; o[nt][3] *= a1;
            }
            m0 = mn0; m1 = mn1;

            uint32_t pa[4][4], pl[4][4];
            float sum0 = 0.0f, sum1 = 0.0f;
#pragma unroll
            for (int nt = 0; nt < 8; ++nt) {
                const float p0 = __expf(s[nt][0] - mn0);
                const float p1 = __expf(s[nt][1] - mn0);
                const float p2 = __expf(s[nt][2] - mn1);
                const float p3 = __expf(s[nt][3] - mn1);
                sum0 += p0 + p1;
                sum1 += p2 + p3;
                uint32_t h01, l01, h23, l23;
                split2(p0, p1, h01, l01);
                split2(p2, p3, h23, l23);
                const int ks = nt >> 1;
                const int off = (nt & 1) * 2;
                pa[ks][off]     = h01;
                pa[ks][off + 1] = h23;
                pl[ks][off]     = l01;
                pl[ks][off + 1] = l23;
            }
            sum0 += __shfl_xor_sync(0xffffffffu, sum0, 1);
            sum0 += __shfl_xor_sync(0xffffffffu, sum0, 2);
            sum1 += __shfl_xor_sync(0xffffffffu, sum1, 1);
            sum1 += __shfl_xor_sync(0xffffffffu, sum1, 2);
            l0 += sum0; l1 += sum1;

#pragma unroll
            for (int ks = 0; ks < 4; ++ks) {
#pragma unroll
                for (int nto = 0; nto < 8; ++nto) {
                    uint32_t bh0, bh1, bl0, bl1;
                    ldsm_x4(bh0, bh1, bl0, bl1,
                            vbase + (uint32_t)(((nto * 8) * FT_LD + ks * 16) * 2));
                    mma_bf16(o[nto], pa[ks], bh0, bh1);
                    mma_bf16(o[nto], pa[ks], bl0, bl1);
                    mma_bf16(o[nto], pl[ks], bh0, bh1);
                }
            }
        }
        __syncthreads();
    }

    {
        const float r0v = 1.0f / l0;
        const float r1v = 1.0f / l1;
        float* Og = Out + (size_t)(b * SEQ + q0 + mb) * HDIM;
#pragma unroll
        for (int nto = 0; nto < 8; ++nto) {
            const int col = nto * 8 + c_fr;
            float2 v0, v1;
            v0.x = o[nto][0] * r0v; v0.y = o[nto][1] * r0v;
            v1.x = o[nto][2] * r1v; v1.y = o[nto][3] * r1v;
            *(float2*)(Og + (size_t)r_fr * HDIM + col)       = v0;
            *(float2*)(Og + (size_t)(r_fr + 8) * HDIM + col) = v1;
        }
    }
}

// ---------------------------------------------------------------------------
extern "C" void kernel_launch(void* const* d_in, const int* in_sizes, int n_in,
                              void* d_out, int out_size)
{
    const float* X  = (const float*)d_in[0];   // [512,256,384]
    const float* Wk = (const float*)d_in[1];   // [384,64]
    const float* Wq = (const float*)d_in[2];   // [384,64]
    const float* Wv = (const float*)d_in[3];   // [384,64]
    float* Out = (float*)d_out;                // [512,256,64]

    (void)in_sizes; (void)n_in; (void)out_size;

    cudaFuncSetAttribute(proj_kernel,
                         cudaFuncAttributeMaxDynamicSharedMemorySize, PJ_SMEM_BYTES);
    cudaFuncSetAttribute(attn_kernel,
                         cudaFuncAttributeMaxDynamicSharedMemorySize, AT_SMEM_BYTES);

    wconv_kernel<<<288, 256>>>(Wq, Wk, Wv);
    proj_kernel<<<NROWS / 128, 256, PJ_SMEM_BYTES>>>(X);

    dim3 grid(2, BATCH);
    attn_kernel<<<grid, 256, AT_SMEM_BYTES>>>(Out);
}

// round 11
// speedup vs baseline: 1.9122x; 1.4383x over previous
#include <cuda_runtime.h>
#include <cuda_fp16.h>
#include <cstdint>

#define BATCH 512
#define SEQ   256
#define EMBED 384
#define HDIM  64
#define NROWS (BATCH * SEQ)   // 131072

typedef uint16_t half_t;

// ---------------------------------------------------------------------------
// Global scratch (fp16):
//   Qh/Ql: [b][s][d] split fp16 (A operand of S)
//   Kh:    [b][s][d] single fp16 (B operand of S)
//   Vth:   [b][d][s] single fp16 (B operand of PV)
//   Wh:    [mat][n][k] single fp16
// ---------------------------------------------------------------------------
__device__ half_t g_Qh[(size_t)NROWS * HDIM];
__device__ half_t g_Ql[(size_t)NROWS * HDIM];
__device__ half_t g_Kh[(size_t)NROWS * HDIM];
__device__ half_t g_Vth[(size_t)BATCH * HDIM * SEQ];
__device__ half_t g_Wh[3 * HDIM * EMBED];

// ---------------------------------------------------------------------------
__device__ __forceinline__ void mma_f16(float* d, const uint32_t* a,
                                        uint32_t b0, uint32_t b1) {
    asm volatile(
        "mma.sync.aligned.m16n8k16.row.col.f32.f16.f16.f32 "
        "{%0,%1,%2,%3}, {%4,%5,%6,%7}, {%8,%9}, {%0,%1,%2,%3};"
        : "+f"(d[0]), "+f"(d[1]), "+f"(d[2]), "+f"(d[3])
        : "r"(a[0]), "r"(a[1]), "r"(a[2]), "r"(a[3]), "r"(b0), "r"(b1));
}

__device__ __forceinline__ void ldsm_x4(uint32_t& r0, uint32_t& r1,
                                        uint32_t& r2, uint32_t& r3,
                                        uint32_t addr) {
    asm volatile(
        "ldmatrix.sync.aligned.m8n8.x4.shared.b16 {%0,%1,%2,%3}, [%4];"
        : "=r"(r0), "=r"(r1), "=r"(r2), "=r"(r3) : "r"(addr));
}

// split x,y into fp16 hi pair + fp16 lo pair
__device__ __forceinline__ void split2h(float x, float y, uint32_t& h, uint32_t& l) {
    const __half2 hh = __floats2half2_rn(x, y);
    const float lx = x - __half2float(__low2half(hh));
    const float ly = y - __half2float(__high2half(hh));
    const __half2 ll = __floats2half2_rn(lx, ly);
    h = *(const uint32_t*)&hh;
    l = *(const uint32_t*)&ll;
}
__device__ __forceinline__ uint32_t pack2h(float x, float y) {
    const __half2 hh = __floats2half2_rn(x, y);
    return *(const uint32_t*)&hh;
}

// ---------------------------------------------------------------------------
// W convert: fp32 [k][n] -> fp16 [mat][n][k]
// ---------------------------------------------------------------------------
__global__ void wconv_kernel(const float* __restrict__ Wq,
                             const float* __restrict__ Wk,
                             const float* __restrict__ Wv)
{
    const int idx = blockIdx.x * 256 + threadIdx.x;   // 73728
    const int mat = idx / (HDIM * EMBED);
    const int rem = idx % (HDIM * EMBED);
    const int n = rem / EMBED;
    const int k = rem % EMBED;
    const float* W = (mat == 0) ? Wq : ((mat == 1) ? Wk : Wv);
    const __half h = __float2half_rn(W[(size_t)k * HDIM + n]);
    g_Wh[idx] = *(const half_t*)&h;
}

// ---------------------------------------------------------------------------
// Projection: M=128, N=192 (Q|K|V), K=384 in 6 chunks of 64.
// 2-pass fp16: acc += Ah*B + Al*B (A = X split fp16, B = W single fp16).
// Double-buffered chunks; all fragments via ldmatrix.x4.
// ---------------------------------------------------------------------------
#define AK_LD 72
#define OFF_AH 0
#define OFF_AL (128 * AK_LD)
#define OFF_B  (2 * 128 * AK_LD)
#define CH_HALVES (OFF_B + 192 * AK_LD)        // 32256 halves / buffer
#define ST_LD 196
#define PJ_SMEM_BYTES (2 * CH_HALVES * 2)      // 129024 (fp32 stage 100KB fits)

__global__ __launch_bounds__(256) void proj_kernel(const float* __restrict__ X)
{
    extern __shared__ char smraw[];
    float* stage = (float*)smraw;
    const uint32_t smb = (uint32_t)__cvta_generic_to_shared(smraw);

    const int tid = threadIdx.x;
    const int lane = tid & 31;
    const int wid = tid >> 5;
    const int warp_m = wid & 3;
    const int warp_n = wid >> 2;
    const int row0 = blockIdx.x * 128;

    const int r_fr = lane >> 2;
    const int c_fr = (lane & 3) * 2;
    const int bli = lane & 7;
    const int bsel = lane >> 3;
    // A-frag ldmatrix lane offset (bytes): m0=(r,kc) m1=(r+8,kc) m2=(r,kc+8) m3=(r+8,kc+8)
    const uint32_t a_lane =
        (uint32_t)((((bsel & 1) * 8 + bli) * AK_LD + (bsel >> 1) * 8) * 2);
    // B-frag lane offset: m0=(n,kc) m1=(n,kc+8) m2=(n+8,kc) m3=(n+8,kc+8)
    const uint32_t b_lane =
        (uint32_t)((((bsel >> 1) * 8 + bli) * AK_LD + (bsel & 1) * 8) * 2);

    float acc[2][12][4];
#pragma unroll
    for (int mt = 0; mt < 2; ++mt)
#pragma unroll
        for (int nt = 0; nt < 12; ++nt)
#pragma unroll
            for (int i = 0; i < 4; ++i) acc[mt][nt][i] = 0.0f;

    auto ldg_x = [&](int c, float4* xr) {
#pragma unroll
        for (int i = 0; i < 8; ++i) {
            const int idx = i * 256 + tid;
            const int m = idx >> 4;
            const int c4 = (idx & 15) * 4;
            xr[i] = *(const float4*)(X + (size_t)(row0 + m) * EMBED + c * 64 + c4);
        }
    };
    auto sts_x = [&](const float4* xr, int part) {
        half_t* Ah = (half_t*)smraw + part * CH_HALVES + OFF_AH;
        half_t* Al = (half_t*)smraw + part * CH_HALVES + OFF_AL;
#pragma unroll
        for (int i = 0; i < 8; ++i) {
            const int idx = i * 256 + tid;
            const int m = idx >> 4;
            const int c4 = (idx & 15) * 4;
            uint32_t h0, l0, h1, l1;
            split2h(xr[i].x, xr[i].y, h0, l0);
            split2h(xr[i].z, xr[i].w, h1, l1);
            uint2 hv, lv;
            hv.x = h0; hv.y = h1; lv.x = l0; lv.y = l1;
            *(uint2*)(Ah + m * AK_LD + c4) = hv;
            *(uint2*)(Al + m * AK_LD + c4) = lv;
        }
    };
    auto ldg_sts_w = [&](int c, int part) {
        half_t* B = (half_t*)smraw + part * CH_HALVES + OFF_B;
#pragma unroll
        for (int i = 0; i < 6; ++i) {
            const int idx = i * 256 + tid;       // 1536 float4
            const int n = idx >> 3;
            const int q = idx & 7;
            const size_t gb = (size_t)n * EMBED + c * 64 + q * 8;
            *(float4*)(B + n * AK_LD + q * 8) = *(const float4*)(g_Wh + gb);
        }
    };

    {
        float4 xr[8];
        ldg_x(0, xr);
        sts_x(xr, 0);
        ldg_sts_w(0, 0);
    }
    __syncthreads();

    for (int c = 0; c < 6; ++c) {
        const int p = c & 1;
        const bool pf = (c < 5);
        float4 xr[8];
        if (pf) ldg_x(c + 1, xr);

        const uint32_t base = smb + (uint32_t)(p * CH_HALVES * 2);
        const uint32_t aB = base + a_lane;
        const uint32_t bB = base + (uint32_t)(OFF_B * 2) + b_lane;

#pragma unroll
        for (int ks = 0; ks < 4; ++ks) {
            const uint32_t kso = (uint32_t)(ks * 32);
            uint32_t ah0[4], ah1[4], al0[4], al1[4];
            ldsm_x4(ah0[0], ah0[1], ah0[2], ah0[3],
                    aB + (uint32_t)((warp_m * 32) * AK_LD * 2) + kso);
            ldsm_x4(ah1[0], ah1[1], ah1[2], ah1[3],
                    aB + (uint32_t)((warp_m * 32 + 16) * AK_LD * 2) + kso);
            ldsm_x4(al0[0], al0[1], al0[2], al0[3],
                    aB + (uint32_t)(OFF_AL * 2) + (uint32_t)((warp_m * 32) * AK_LD * 2) + kso);
            ldsm_x4(al1[0], al1[1], al1[2], al1[3],
                    aB + (uint32_t)(OFF_AL * 2) + (uint32_t)((warp_m * 32 + 16) * AK_LD * 2) + kso);
#pragma unroll
            for (int ntp = 0; ntp < 6; ++ntp) {      // nt pairs
                uint32_t b0e, b1e, b0o, b1o;
                ldsm_x4(b0e, b1e, b0o, b1o,
                        bB + (uint32_t)(((warp_n * 96 + ntp * 16) * AK_LD) * 2) + kso);
                mma_f16(acc[0][2 * ntp],     ah0, b0e, b1e);
                mma_f16(acc[0][2 * ntp],     al0, b0e, b1e);
                mma_f16(acc[1][2 * ntp],     ah1, b0e, b1e);
                mma_f16(acc[1][2 * ntp],     al1, b0e, b1e);
                mma_f16(acc[0][2 * ntp + 1], ah0, b0o, b1o);
                mma_f16(acc[0][2 * ntp + 1], al0, b0o, b1o);
                mma_f16(acc[1][2 * ntp + 1], ah1, b0o, b1o);
                mma_f16(acc[1][2 * ntp + 1], al1, b0o, b1o);
            }
        }

        if (pf) {
            sts_x(xr, 1 - p);
            ldg_sts_w(c + 1, 1 - p);
        }
        __syncthreads();
    }

    // --- stage accumulators (fp32) ---
#pragma unroll
    for (int mt = 0; mt < 2; ++mt) {
        const int r0 = warp_m * 32 + mt * 16 + r_fr;
#pragma unroll
        for (int nt = 0; nt < 12; ++nt) {
            const int col = warp_n * 96 + nt * 8 + c_fr;
            float2 v0, v1;
            v0.x = acc[mt][nt][0]; v0.y = acc[mt][nt][1];
            v1.x = acc[mt][nt][2]; v1.y = acc[mt][nt][3];
            *(float2*)(stage + r0 * ST_LD + col)       = v0;
            *(float2*)(stage + (r0 + 8) * ST_LD + col) = v1;
        }
    }
    __syncthreads();

    const int b = row0 >> 8;
    const int sbase = row0 & 255;

    // --- Q split fp16, K single fp16: [b][s][d] ---
    for (int idx = tid; idx < 2048; idx += 256) {
        const int m = idx >> 4;
        const int q = (idx & 15) * 4;
        const size_t go = (size_t)(row0 + m) * HDIM + q;
        {
            const float4 v = *(const float4*)(stage + m * ST_LD + q);
            uint32_t h0, l0, h1, l1;
            split2h(v.x, v.y, h0, l0);
            split2h(v.z, v.w, h1, l1);
            uint2 hv, lv; hv.x = h0; hv.y = h1; lv.x = l0; lv.y = l1;
            *(uint2*)(g_Qh + go) = hv;
            *(uint2*)(g_Ql + go) = lv;
        }
        {
            const float4 v = *(const float4*)(stage + m * ST_LD + 64 + q);
            uint2 kv;
            kv.x = pack2h(v.x, v.y);
            kv.y = pack2h(v.z, v.w);
            *(uint2*)(g_Kh + go) = kv;
        }
    }
    // --- V single fp16 transposed [b][d][s] ---
    for (int idx = tid; idx < 2048; idx += 256) {
        const int d = idx >> 5;
        const int s0 = (idx & 31) * 4;
        const float v0 = stage[(s0 + 0) * ST_LD + 128 + d];
        const float v1 = stage[(s0 + 1) * ST_LD + 128 + d];
        const float v2 = stage[(s0 + 2) * ST_LD + 128 + d];
        const float v3 = stage[(s0 + 3) * ST_LD + 128 + d];
        uint2 vv;
        vv.x = pack2h(v0, v1);
        vv.y = pack2h(v2, v3);
        *(uint2*)(g_Vth + ((size_t)b * HDIM + d) * SEQ + sbase + s0) = vv;
    }
}

// ---------------------------------------------------------------------------
// FlashAttention-2, 2-pass fp16. Grid (2, 512).
// S: (Qh + Ql) x K (K single fp16). PV: (Ph + Pl) x V (V single fp16).
// K/V tiles single-array -> halved smem and loads.
// ---------------------------------------------------------------------------
#define FT_LD 72
#define BUF_HALVES (2 * 64 * FT_LD)           // Kh,Vh = 9216 halves
#define AT_SMEM_BYTES (2 * BUF_HALVES * 2)    // 36864 bytes

__global__ __launch_bounds__(256) void attn_kernel(float* __restrict__ Out)
{
    extern __shared__ char smr[];
    half_t* const buf[2] = { (half_t*)smr, (half_t*)smr + BUF_HALVES };

    const int tid = threadIdx.x;
    const int lane = tid & 31;
    const int wid = tid >> 5;
    const int r_fr = lane >> 2;
    const int c_fr = (lane & 3) * 2;
    const int mb = wid * 16;

    const int qt = blockIdx.x;          // 0..1
    const int b  = blockIdx.y;
    const int q0 = qt * 128;
    const int njt = qt * 2 + 2;
    const float scale = 0.125f;

    // --- stage Q (spans both buffers), extract A-frags into registers ---
    uint32_t qh[4][4], ql[4][4];
    {
        half_t* Qsh = buf[0];
        half_t* Qsl = buf[0] + 128 * FT_LD;
        const half_t* Qhg = g_Qh + (size_t)(b * SEQ + q0) * HDIM;
        const half_t* Qlg = g_Ql + (size_t)(b * SEQ + q0) * HDIM;
        for (int idx = tid; idx < 1024; idx += 256) {
            const int r = idx >> 3;
            const int q8 = (idx & 7) * 8;
            *(float4*)(Qsh + r * FT_LD + q8) = *(const float4*)(Qhg + r * HDIM + q8);
            *(float4*)(Qsl + r * FT_LD + q8) = *(const float4*)(Qlg + r * HDIM + q8);
        }
        __syncthreads();
#pragma unroll
        for (int ks = 0; ks < 4; ++ks) {
            const int kc = ks * 16 + c_fr;
            qh[ks][0] = *(const uint32_t*)(Qsh + (mb + r_fr) * FT_LD + kc);
            qh[ks][1] = *(const uint32_t*)(Qsh + (mb + r_fr + 8) * FT_LD + kc);
            qh[ks][2] = *(const uint32_t*)(Qsh + (mb + r_fr) * FT_LD + kc + 8);
            qh[ks][3] = *(const uint32_t*)(Qsh + (mb + r_fr + 8) * FT_LD + kc + 8);
            ql[ks][0] = *(const uint32_t*)(Qsl + (mb + r_fr) * FT_LD + kc);
            ql[ks][1] = *(const uint32_t*)(Qsl + (mb + r_fr + 8) * FT_LD + kc);
            ql[ks][2] = *(const uint32_t*)(Qsl + (mb + r_fr) * FT_LD + kc + 8);
            ql[ks][3] = *(const uint32_t*)(Qsl + (mb + r_fr + 8) * FT_LD + kc + 8);
        }
        __syncthreads();
    }

    float o[8][4];
#pragma unroll
    for (int nt = 0; nt < 8; ++nt)
#pragma unroll
        for (int i = 0; i < 4; ++i) o[nt][i] = 0.0f;
    float m0 = -3.4e38f, m1 = -3.4e38f, l0 = 0.0f, l1 = 0.0f;

    const half_t* Khg = g_Kh + (size_t)b * SEQ * HDIM;
    const half_t* Vhg = g_Vth + (size_t)b * HDIM * SEQ;

    auto load_tile = [&](int jt, half_t* dst) {
        half_t* Kh = dst;
        half_t* Vh = dst + 64 * FT_LD;
        const half_t* kh = Khg + (size_t)jt * 64 * HDIM;
        const half_t* vh = Vhg + jt * 64;
        for (int idx = tid; idx < 512; idx += 256) {
            const int r = idx >> 3;
            const int q8 = (idx & 7) * 8;
            *(float4*)(Kh + r * FT_LD + q8) = *(const float4*)(kh + r * HDIM + q8);
            *(float4*)(Vh + r * FT_LD + q8) = *(const float4*)(vh + (size_t)r * SEQ + q8);
        }
    };

    load_tile(0, buf[0]);
    __syncthreads();

    // B-frag lane offset: m0=(n,kc) m1=(n,kc+8) m2=(n+8,kc) m3=(n+8,kc+8)
    const int bli = lane & 7;
    const int bsel = lane >> 3;
    const uint32_t b_lane =
        (uint32_t)((((bsel >> 1) * 8 + bli) * FT_LD + (bsel & 1) * 8) * 2);

    for (int jt = 0; jt < njt; ++jt) {
        half_t* cur = buf[jt & 1];
        if (jt + 1 < njt) load_tile(jt + 1, buf[(jt + 1) & 1]);

        const bool active = (jt * 64) <= (q0 + mb + 15);
        if (active) {
            const uint32_t kbase = (uint32_t)__cvta_generic_to_shared(cur) + b_lane;
            const uint32_t vbase = kbase + (uint32_t)(64 * FT_LD * 2);

            // --- S = Q K^T (2 passes) ---
            float s[8][4];
#pragma unroll
            for (int nt = 0; nt < 8; ++nt)
#pragma unroll
                for (int i = 0; i < 4; ++i) s[nt][i] = 0.0f;
#pragma unroll
            for (int ks = 0; ks < 4; ++ks) {
#pragma unroll
                for (int ntp = 0; ntp < 4; ++ntp) {
                    uint32_t b0e, b1e, b0o, b1o;
                    ldsm_x4(b0e, b1e, b0o, b1o,
                            kbase + (uint32_t)(((ntp * 16) * FT_LD + ks * 16) * 2));
                    mma_f16(s[2 * ntp],     qh[ks], b0e, b1e);
                    mma_f16(s[2 * ntp],     ql[ks], b0e, b1e);
                    mma_f16(s[2 * ntp + 1], qh[ks], b0o, b1o);
                    mma_f16(s[2 * ntp + 1], ql[ks], b0o, b1o);
                }
            }

            // --- scale + causal mask ---
            const int rowg0 = q0 + mb + r_fr;
            const int rowg1 = rowg0 + 8;
            const bool needm = (jt * 64 + 63) > (q0 + mb);
#pragma unroll
            for (int nt = 0; nt < 8; ++nt) {
                const int colg = jt * 64 + nt * 8 + c_fr;
                s[nt][0] *= scale; s[nt][1] *= scale;
                s[nt][2] *= scale; s[nt][3] *= scale;
                if (needm) {
                    if (colg     > rowg0) s[nt][0] = -3.4e38f;
                    if (colg + 1 > rowg0) s[nt][1] = -3.4e38f;
                    if (colg     > rowg1) s[nt][2] = -3.4e38f;
                    if (colg + 1 > rowg1) s[nt][3] = -3.4e38f;
                }
            }

            // --- online softmax ---
            float mx0 = -3.4e38f, mx1 = -3.4e38f;
#pragma unroll
            for (int nt = 0; nt < 8; ++nt) {
                mx0 = fmaxf(mx0, fmaxf(s[nt][0], s[nt][1]));
                mx1 = fmaxf(mx1, fmaxf(s[nt][2], s[nt][3]));
            }
            mx0 = fmaxf(mx0, __shfl_xor_sync(0xffffffffu, mx0, 1));
            mx0 = fmaxf(mx0, __shfl_xor_sync(0xffffffffu, mx0, 2));
            mx1 = fmaxf(mx1, __shfl_xor_sync(0xffffffffu, mx1, 1));
            mx1 = fmaxf(mx1, __shfl_xor_sync(0xffffffffu, mx1, 2));
            const float mn0 = fmaxf(m0, mx0);
            const float mn1 = fmaxf(m1, mx1);
            const float a0 = __expf(m0 - mn0);
            const float a1 = __expf(m1 - mn1);
            l0 *= a0; l1 *= a1;
#pragma unroll
            for (int nt = 0; nt < 8; ++nt) {
                o[nt][0] *= a0; o[nt][1] *= a0;
                o[nt][2] *= a1; o[nt][3] *= a1;
            }
            m0 = mn0; m1 = mn1;

            // --- P = exp(S-m) -> fp16 split A-frags in regs ---
            uint32_t pa[4][4], pl[4][4];
            float sum0 = 0.0f, sum1 = 0.0f;
#pragma unroll
            for (int nt = 0; nt < 8; ++nt) {
                const float p0 = __expf(s[nt][0] - mn0);
                const float p1 = __expf(s[nt][1] - mn0);
                const float p2 = __expf(s[nt][2] - mn1);
                const float p3 = __expf(s[nt][3] - mn1);
                sum0 += p0 + p1;
                sum1 += p2 + p3;
                uint32_t h01, l01, h23, l23;
                split2h(p0, p1, h01, l01);
                split2h(p2, p3, h23, l23);
                const int ks = nt >> 1;
                const int off = (nt & 1) * 2;
                pa[ks][off]     = h01;
                pa[ks][off + 1] = h23;
                pl[ks][off]     = l01;
                pl[ks][off + 1] = l23;
            }
            sum0 += __shfl_xor_sync(0xffffffffu, sum0, 1);
            sum0 += __shfl_xor_sync(0xffffffffu, sum0, 2);
            sum1 += __shfl_xor_sync(0xffffffffu, sum1, 1);
            sum1 += __shfl_xor_sync(0xffffffffu, sum1, 2);
            l0 += sum0; l1 += sum1;

            // --- O += P V (2 passes) ---
#pragma unroll
            for (int ks = 0; ks < 4; ++ks) {
#pragma unroll
                for (int ntp = 0; ntp < 4; ++ntp) {
                    uint32_t b0e, b1e, b0o, b1o;
                    ldsm_x4(b0e, b1e, b0o, b1o,
                            vbase + (uint32_t)(((ntp * 16) * FT_LD + ks * 16) * 2));
                    mma_f16(o[2 * ntp],     pa[ks], b0e, b1e);
                    mma_f16(o[2 * ntp],     pl[ks], b0e, b1e);
                    mma_f16(o[2 * ntp + 1], pa[ks], b0o, b1o);
                    mma_f16(o[2 * ntp + 1], pl[ks], b0o, b1o);
                }
            }
        }
        __syncthreads();
    }

    // --- epilogue ---
    {
        const float r0v = 1.0f / l0;
        const float r1v = 1.0f / l1;
        float* Og = Out + (size_t)(b * SEQ + q0 + mb) * HDIM;
#pragma unroll
        for (int nto = 0; nto < 8; ++nto) {
            const int col = nto * 8 + c_fr;
            float2 v0, v1;
            v0.x = o[nto][0] * r0v; v0.y = o[nto][1] * r0v;
            v1.x = o[nto][2] * r1v; v1.y = o[nto][3] * r1v;
            *(float2*)(Og + (size_t)r_fr * HDIM + col)       = v0;
            *(float2*)(Og + (size_t)(r_fr + 8) * HDIM + col) = v1;
        }
    }
}

// ---------------------------------------------------------------------------
extern "C" void kernel_launch(void* const* d_in, const int* in_sizes, int n_in,
                              void* d_out, int out_size)
{
    const float* X  = (const float*)d_in[0];   // [512,256,384]
    const float* Wk = (const float*)d_in[1];   // [384,64]
    const float* Wq = (const float*)d_in[2];   // [384,64]
    const float* Wv = (const float*)d_in[3];   // [384,64]
    float* Out = (float*)d_out;                // [512,256,64]

    (void)in_sizes; (void)n_in; (void)out_size;

    cudaFuncSetAttribute(proj_kernel,
                         cudaFuncAttributeMaxDynamicSharedMemorySize, PJ_SMEM_BYTES);
    cudaFuncSetAttribute(attn_kernel,
                         cudaFuncAttributeMaxDynamicSharedMemorySize, AT_SMEM_BYTES);

    wconv_kernel<<<288, 256>>>(Wq, Wk, Wv);
    proj_kernel<<<NROWS / 128, 256, PJ_SMEM_BYTES>>>(X);

    dim3 grid(2, BATCH);
    attn_kernel<<<grid, 256, AT_SMEM_BYTES>>>(Out);
}

// round 12
// speedup vs baseline: 2.2376x; 1.1702x over previous
#include <cuda_runtime.h>
#include <cuda_fp16.h>
#include <cstdint>

#define BATCH 512
#define SEQ   256
#define EMBED 384
#define HDIM  64
#define NROWS (BATCH * SEQ)   // 131072

typedef uint16_t half_t;

// ---------------------------------------------------------------------------
// Global scratch (fp16):
//   Qh/Ql: [b][s][d] split fp16, PRE-SCALED by 1/8 (A operand of S)
//   Kh:    [b][s][d] single fp16 (B operand of S)
//   Vth:   [b][d][s] single fp16 (B operand of PV)
//   Wh:    [mat][n][k] single fp16
// ---------------------------------------------------------------------------
__device__ half_t g_Qh[(size_t)NROWS * HDIM];
__device__ half_t g_Ql[(size_t)NROWS * HDIM];
__device__ half_t g_Kh[(size_t)NROWS * HDIM];
__device__ half_t g_Vth[(size_t)BATCH * HDIM * SEQ];
__device__ half_t g_Wh[3 * HDIM * EMBED];

// ---------------------------------------------------------------------------
__device__ __forceinline__ void mma_f16(float* d, const uint32_t* a,
                                        uint32_t b0, uint32_t b1) {
    asm volatile(
        "mma.sync.aligned.m16n8k16.row.col.f32.f16.f16.f32 "
        "{%0,%1,%2,%3}, {%4,%5,%6,%7}, {%8,%9}, {%0,%1,%2,%3};"
        : "+f"(d[0]), "+f"(d[1]), "+f"(d[2]), "+f"(d[3])
        : "r"(a[0]), "r"(a[1]), "r"(a[2]), "r"(a[3]), "r"(b0), "r"(b1));
}

__device__ __forceinline__ void ldsm_x4(uint32_t& r0, uint32_t& r1,
                                        uint32_t& r2, uint32_t& r3,
                                        uint32_t addr) {
    asm volatile(
        "ldmatrix.sync.aligned.m8n8.x4.shared.b16 {%0,%1,%2,%3}, [%4];"
        : "=r"(r0), "=r"(r1), "=r"(r2), "=r"(r3) : "r"(addr));
}

__device__ __forceinline__ void split2h(float x, float y, uint32_t& h, uint32_t& l) {
    const __half2 hh = __floats2half2_rn(x, y);
    const float lx = x - __half2float(__low2half(hh));
    const float ly = y - __half2float(__high2half(hh));
    const __half2 ll = __floats2half2_rn(lx, ly);
    h = *(const uint32_t*)&hh;
    l = *(const uint32_t*)&ll;
}
__device__ __forceinline__ uint32_t pack2h(float x, float y) {
    const __half2 hh = __floats2half2_rn(x, y);
    return *(const uint32_t*)&hh;
}

// ---------------------------------------------------------------------------
// W convert: fp32 [k][n] -> fp16 [mat][n][k]
// ---------------------------------------------------------------------------
__global__ void wconv_kernel(const float* __restrict__ Wq,
                             const float* __restrict__ Wk,
                             const float* __restrict__ Wv)
{
    const int idx = blockIdx.x * 256 + threadIdx.x;   // 73728
    const int mat = idx / (HDIM * EMBED);
    const int rem = idx % (HDIM * EMBED);
    const int n = rem / EMBED;
    const int k = rem % EMBED;
    const float* W = (mat == 0) ? Wq : ((mat == 1) ? Wk : Wv);
    const __half h = __float2half_rn(W[(size_t)k * HDIM + n]);
    g_Wh[idx] = *(const half_t*)&h;
}

// ---------------------------------------------------------------------------
// Projection: M=128, N=192 (Q|K|V), K=384 in 6 chunks of 64.
// 2-pass fp16 (X split, W single). Double-buffered; ldmatrix fragments.
// ---------------------------------------------------------------------------
#define AK_LD 72
#define OFF_AH 0
#define OFF_AL (128 * AK_LD)
#define OFF_B  (2 * 128 * AK_LD)
#define CH_HALVES (OFF_B + 192 * AK_LD)        // 32256 halves / buffer
#define ST_LD 196
#define PJ_SMEM_BYTES (2 * CH_HALVES * 2)      // 129024

__global__ __launch_bounds__(256) void proj_kernel(const float* __restrict__ X)
{
    extern __shared__ char smraw[];
    float* stage = (float*)smraw;
    const uint32_t smb = (uint32_t)__cvta_generic_to_shared(smraw);

    const int tid = threadIdx.x;
    const int lane = tid & 31;
    const int wid = tid >> 5;
    const int warp_m = wid & 3;
    const int warp_n = wid >> 2;
    const int row0 = blockIdx.x * 128;

    const int r_fr = lane >> 2;
    const int c_fr = (lane & 3) * 2;
    const int bli = lane & 7;
    const int bsel = lane >> 3;
    const uint32_t a_lane =
        (uint32_t)((((bsel & 1) * 8 + bli) * AK_LD + (bsel >> 1) * 8) * 2);
    const uint32_t b_lane =
        (uint32_t)((((bsel >> 1) * 8 + bli) * AK_LD + (bsel & 1) * 8) * 2);

    float acc[2][12][4];
#pragma unroll
    for (int mt = 0; mt < 2; ++mt)
#pragma unroll
        for (int nt = 0; nt < 12; ++nt)
#pragma unroll
            for (int i = 0; i < 4; ++i) acc[mt][nt][i] = 0.0f;

    auto ldg_x = [&](int c, float4* xr) {
#pragma unroll
        for (int i = 0; i < 8; ++i) {
            const int idx = i * 256 + tid;
            const int m = idx >> 4;
            const int c4 = (idx & 15) * 4;
            xr[i] = *(const float4*)(X + (size_t)(row0 + m) * EMBED + c * 64 + c4);
        }
    };
    auto sts_x = [&](const float4* xr, int part) {
        half_t* Ah = (half_t*)smraw + part * CH_HALVES + OFF_AH;
        half_t* Al = (half_t*)smraw + part * CH_HALVES + OFF_AL;
#pragma unroll
        for (int i = 0; i < 8; ++i) {
            const int idx = i * 256 + tid;
            const int m = idx >> 4;
            const int c4 = (idx & 15) * 4;
            uint32_t h0, l0, h1, l1;
            split2h(xr[i].x, xr[i].y, h0, l0);
            split2h(xr[i].z, xr[i].w, h1, l1);
            uint2 hv, lv;
            hv.x = h0; hv.y = h1; lv.x = l0; lv.y = l1;
            *(uint2*)(Ah + m * AK_LD + c4) = hv;
            *(uint2*)(Al + m * AK_LD + c4) = lv;
        }
    };
    auto ldg_sts_w = [&](int c, int part) {
        half_t* B = (half_t*)smraw + part * CH_HALVES + OFF_B;
#pragma unroll
        for (int i = 0; i < 6; ++i) {
            const int idx = i * 256 + tid;
            const int n = idx >> 3;
            const int q = idx & 7;
            const size_t gb = (size_t)n * EMBED + c * 64 + q * 8;
            *(float4*)(B + n * AK_LD + q * 8) = *(const float4*)(g_Wh + gb);
        }
    };

    {
        float4 xr[8];
        ldg_x(0, xr);
        sts_x(xr, 0);
        ldg_sts_w(0, 0);
    }
    __syncthreads();

    for (int c = 0; c < 6; ++c) {
        const int p = c & 1;
        const bool pf = (c < 5);
        float4 xr[8];
        if (pf) ldg_x(c + 1, xr);

        const uint32_t base = smb + (uint32_t)(p * CH_HALVES * 2);
        const uint32_t aB = base + a_lane;
        const uint32_t bB = base + (uint32_t)(OFF_B * 2) + b_lane;

#pragma unroll
        for (int ks = 0; ks < 4; ++ks) {
            const uint32_t kso = (uint32_t)(ks * 32);
            uint32_t ah0[4], ah1[4], al0[4], al1[4];
            ldsm_x4(ah0[0], ah0[1], ah0[2], ah0[3],
                    aB + (uint32_t)((warp_m * 32) * AK_LD * 2) + kso);
            ldsm_x4(ah1[0], ah1[1], ah1[2], ah1[3],
                    aB + (uint32_t)((warp_m * 32 + 16) * AK_LD * 2) + kso);
            ldsm_x4(al0[0], al0[1], al0[2], al0[3],
                    aB + (uint32_t)(OFF_AL * 2) + (uint32_t)((warp_m * 32) * AK_LD * 2) + kso);
            ldsm_x4(al1[0], al1[1], al1[2], al1[3],
                    aB + (uint32_t)(OFF_AL * 2) + (uint32_t)((warp_m * 32 + 16) * AK_LD * 2) + kso);
#pragma unroll
            for (int ntp = 0; ntp < 6; ++ntp) {
                uint32_t b0e, b1e, b0o, b1o;
                ldsm_x4(b0e, b1e, b0o, b1o,
                        bB + (uint32_t)(((warp_n * 96 + ntp * 16) * AK_LD) * 2) + kso);
                mma_f16(acc[0][2 * ntp],     ah0, b0e, b1e);
                mma_f16(acc[0][2 * ntp],     al0, b0e, b1e);
                mma_f16(acc[1][2 * ntp],     ah1, b0e, b1e);
                mma_f16(acc[1][2 * ntp],     al1, b0e, b1e);
                mma_f16(acc[0][2 * ntp + 1], ah0, b0o, b1o);
                mma_f16(acc[0][2 * ntp + 1], al0, b0o, b1o);
                mma_f16(acc[1][2 * ntp + 1], ah1, b0o, b1o);
                mma_f16(acc[1][2 * ntp + 1], al1, b0o, b1o);
            }
        }

        if (pf) {
            sts_x(xr, 1 - p);
            ldg_sts_w(c + 1, 1 - p);
        }
        __syncthreads();
    }

    // --- stage accumulators (fp32) ---
#pragma unroll
    for (int mt = 0; mt < 2; ++mt) {
        const int r0 = warp_m * 32 + mt * 16 + r_fr;
#pragma unroll
        for (int nt = 0; nt < 12; ++nt) {
            const int col = warp_n * 96 + nt * 8 + c_fr;
            float2 v0, v1;
            v0.x = acc[mt][nt][0]; v0.y = acc[mt][nt][1];
            v1.x = acc[mt][nt][2]; v1.y = acc[mt][nt][3];
            *(float2*)(stage + r0 * ST_LD + col)       = v0;
            *(float2*)(stage + (r0 + 8) * ST_LD + col) = v1;
        }
    }
    __syncthreads();

    const int b = row0 >> 8;
    const int sbase = row0 & 255;

    // --- Q split fp16 PRE-SCALED by 1/8; K single fp16: [b][s][d] ---
    for (int idx = tid; idx < 2048; idx += 256) {
        const int m = idx >> 4;
        const int q = (idx & 15) * 4;
        const size_t go = (size_t)(row0 + m) * HDIM + q;
        {
            const float4 v = *(const float4*)(stage + m * ST_LD + q);
            uint32_t h0, l0, h1, l1;
            split2h(v.x * 0.125f, v.y * 0.125f, h0, l0);
            split2h(v.z * 0.125f, v.w * 0.125f, h1, l1);
            uint2 hv, lv; hv.x = h0; hv.y = h1; lv.x = l0; lv.y = l1;
            *(uint2*)(g_Qh + go) = hv;
            *(uint2*)(g_Ql + go) = lv;
        }
        {
            const float4 v = *(const float4*)(stage + m * ST_LD + 64 + q);
            uint2 kv;
            kv.x = pack2h(v.x, v.y);
            kv.y = pack2h(v.z, v.w);
            *(uint2*)(g_Kh + go) = kv;
        }
    }
    // --- V single fp16 transposed [b][d][s] ---
    for (int idx = tid; idx < 2048; idx += 256) {
        const int d = idx >> 5;
        const int s0 = (idx & 31) * 4;
        const float v0 = stage[(s0 + 0) * ST_LD + 128 + d];
        const float v1 = stage[(s0 + 1) * ST_LD + 128 + d];
        const float v2 = stage[(s0 + 2) * ST_LD + 128 + d];
        const float v3 = stage[(s0 + 3) * ST_LD + 128 + d];
        uint2 vv;
        vv.x = pack2h(v0, v1);
        vv.y = pack2h(v2, v3);
        *(uint2*)(g_Vth + ((size_t)b * HDIM + d) * SEQ + sbase + s0) = vv;
    }
}

// ---------------------------------------------------------------------------
// FlashAttention-2, 2-pass fp16, occupancy 2 (smem 36.9KB, regs capped 128).
// Scale pre-folded into Q.
// ---------------------------------------------------------------------------
#define FT_LD 72
#define BUF_HALVES (2 * 64 * FT_LD)           // Kh,Vh = 9216 halves
#define AT_SMEM_BYTES (2 * BUF_HALVES * 2)    // 36864 bytes

__global__ __launch_bounds__(256, 2) void attn_kernel(float* __restrict__ Out)
{
    extern __shared__ char smr[];
    half_t* const buf[2] = { (half_t*)smr, (half_t*)smr + BUF_HALVES };

    const int tid = threadIdx.x;
    const int lane = tid & 31;
    const int wid = tid >> 5;
    const int r_fr = lane >> 2;
    const int c_fr = (lane & 3) * 2;
    const int mb = wid * 16;

    const int qt = blockIdx.x;          // 0..1
    const int b  = blockIdx.y;
    const int q0 = qt * 128;
    const int njt = qt * 2 + 2;

    // --- stage Q, extract A-frags into registers ---
    uint32_t qh[4][4], ql[4][4];
    {
        half_t* Qsh = buf[0];
        half_t* Qsl = buf[0] + 128 * FT_LD;
        const half_t* Qhg = g_Qh + (size_t)(b * SEQ + q0) * HDIM;
        const half_t* Qlg = g_Ql + (size_t)(b * SEQ + q0) * HDIM;
        for (int idx = tid; idx < 1024; idx += 256) {
            const int r = idx >> 3;
            const int q8 = (idx & 7) * 8;
            *(float4*)(Qsh + r * FT_LD + q8) = *(const float4*)(Qhg + r * HDIM + q8);
            *(float4*)(Qsl + r * FT_LD + q8) = *(const float4*)(Qlg + r * HDIM + q8);
        }
        __syncthreads();
#pragma unroll
        for (int ks = 0; ks < 4; ++ks) {
            const int kc = ks * 16 + c_fr;
            qh[ks][0] = *(const uint32_t*)(Qsh + (mb + r_fr) * FT_LD + kc);
            qh[ks][1] = *(const uint32_t*)(Qsh + (mb + r_fr + 8) * FT_LD + kc);
            qh[ks][2] = *(const uint32_t*)(Qsh + (mb + r_fr) * FT_LD + kc + 8);
            qh[ks][3] = *(const uint32_t*)(Qsh + (mb + r_fr + 8) * FT_LD + kc + 8);
            ql[ks][0] = *(const uint32_t*)(Qsl + (mb + r_fr) * FT_LD + kc);
            ql[ks][1] = *(const uint32_t*)(Qsl + (mb + r_fr + 8) * FT_LD + kc);
            ql[ks][2] = *(const uint32_t*)(Qsl + (mb + r_fr) * FT_LD + kc + 8);
            ql[ks][3] = *(const uint32_t*)(Qsl + (mb + r_fr + 8) * FT_LD + kc + 8);
        }
        __syncthreads();
    }

    float o[8][4];
#pragma unroll
    for (int nt = 0; nt < 8; ++nt)
#pragma unroll
        for (int i = 0; i < 4; ++i) o[nt][i] = 0.0f;
    float m0 = -3.4e38f, m1 = -3.4e38f, l0 = 0.0f, l1 = 0.0f;

    const half_t* Khg = g_Kh + (size_t)b * SEQ * HDIM;
    const half_t* Vhg = g_Vth + (size_t)b * HDIM * SEQ;

    auto load_tile = [&](int jt, half_t* dst) {
        half_t* Kh = dst;
        half_t* Vh = dst + 64 * FT_LD;
        const half_t* kh = Khg + (size_t)jt * 64 * HDIM;
        const half_t* vh = Vhg + jt * 64;
        for (int idx = tid; idx < 512; idx += 256) {
            const int r = idx >> 3;
            const int q8 = (idx & 7) * 8;
            *(float4*)(Kh + r * FT_LD + q8) = *(const float4*)(kh + r * HDIM + q8);
            *(float4*)(Vh + r * FT_LD + q8) = *(const float4*)(vh + (size_t)r * SEQ + q8);
        }
    };

    load_tile(0, buf[0]);
    __syncthreads();

    const int bli = lane & 7;
    const int bsel = lane >> 3;
    const uint32_t b_lane =
        (uint32_t)((((bsel >> 1) * 8 + bli) * FT_LD + (bsel & 1) * 8) * 2);

    for (int jt = 0; jt < njt; ++jt) {
        half_t* cur = buf[jt & 1];
        if (jt + 1 < njt) load_tile(jt + 1, buf[(jt + 1) & 1]);

        const bool active = (jt * 64) <= (q0 + mb + 15);
        if (active) {
            const uint32_t kbase = (uint32_t)__cvta_generic_to_shared(cur) + b_lane;
            const uint32_t vbase = kbase + (uint32_t)(64 * FT_LD * 2);

            // --- S = Q K^T (2 passes; scale pre-folded) ---
            float s[8][4];
#pragma unroll
            for (int nt = 0; nt < 8; ++nt)
#pragma unroll
                for (int i = 0; i < 4; ++i) s[nt][i] = 0.0f;
#pragma unroll
            for (int ks = 0; ks < 4; ++ks) {
#pragma unroll
                for (int ntp = 0; ntp < 4; ++ntp) {
                    uint32_t b0e, b1e, b0o, b1o;
                    ldsm_x4(b0e, b1e, b0o, b1o,
                            kbase + (uint32_t)(((ntp * 16) * FT_LD + ks * 16) * 2));
                    mma_f16(s[2 * ntp],     qh[ks], b0e, b1e);
                    mma_f16(s[2 * ntp],     ql[ks], b0e, b1e);
                    mma_f16(s[2 * ntp + 1], qh[ks], b0o, b1o);
                    mma_f16(s[2 * ntp + 1], ql[ks], b0o, b1o);
                }
            }

            // --- causal mask (only needed on diagonal tiles) ---
            const int rowg0 = q0 + mb + r_fr;
            const int rowg1 = rowg0 + 8;
            if ((jt * 64 + 63) > (q0 + mb)) {
#pragma unroll
                for (int nt = 0; nt < 8; ++nt) {
                    const int colg = jt * 64 + nt * 8 + c_fr;
                    if (colg     > rowg0) s[nt][0] = -3.4e38f;
                    if (colg + 1 > rowg0) s[nt][1] = -3.4e38f;
                    if (colg     > rowg1) s[nt][2] = -3.4e38f;
                    if (colg + 1 > rowg1) s[nt][3] = -3.4e38f;
                }
            }

            // --- online softmax ---
            float mx0 = -3.4e38f, mx1 = -3.4e38f;
#pragma unroll
            for (int nt = 0; nt < 8; ++nt) {
                mx0 = fmaxf(mx0, fmaxf(s[nt][0], s[nt][1]));
                mx1 = fmaxf(mx1, fmaxf(s[nt][2], s[nt][3]));
            }
            mx0 = fmaxf(mx0, __shfl_xor_sync(0xffffffffu, mx0, 1));
            mx0 = fmaxf(mx0, __shfl_xor_sync(0xffffffffu, mx0, 2));
            mx1 = fmaxf(mx1, __shfl_xor_sync(0xffffffffu, mx1, 1));
            mx1 = fmaxf(mx1, __shfl_xor_sync(0xffffffffu, mx1, 2));
            const float mn0 = fmaxf(m0, mx0);
            const float mn1 = fmaxf(m1, mx1);
            const float a0 = __expf(m0 - mn0);
            const float a1 = __expf(m1 - mn1);
            l0 *= a0; l1 *= a1;
#pragma unroll
            for (int nt = 0; nt < 8; ++nt) {
                o[nt][0] *= a0; o[nt][1] *= a0;
                o[nt][2] *= a1; o[nt][3] *= a1;
            }
            m0 = mn0; m1 = mn1;

            // --- P = exp(S-m) -> fp16 split A-frags ---
            uint32_t pa[4][4], pl[4][4];
            float sum0 = 0.0f, sum1 = 0.0f;
#pragma unroll
            for (int nt = 0; nt < 8; ++nt) {
                const float p0 = __expf(s[nt][0] - mn0);
                const float p1 = __expf(s[nt][1] - mn0);
                const float p2 = __expf(s[nt][2] - mn1);
                const float p3 = __expf(s[nt][3] - mn1);
                sum0 += p0 + p1;
                sum1 += p2 + p3;
                uint32_t h01, l01, h23, l23;
                split2h(p0, p1, h01, l01);
                split2h(p2, p3, h23, l23);
                const int ks = nt >> 1;
                const int off = (nt & 1) * 2;
                pa[ks][off]     = h01;
                pa[ks][off + 1] = h23;
                pl[ks][off]     = l01;
                pl[ks][off + 1] = l23;
            }
            sum0 += __shfl_xor_sync(0xffffffffu, sum0, 1);
            sum0 += __shfl_xor_sync(0xffffffffu, sum0, 2);
            sum1 += __shfl_xor_sync(0xffffffffu, sum1, 1);
            sum1 += __shfl_xor_sync(0xffffffffu, sum1, 2);
            l0 += sum0; l1 += sum1;

            // --- O += P V (2 passes) ---
#pragma unroll
            for (int ks = 0; ks < 4; ++ks) {
#pragma unroll
                for (int ntp = 0; ntp < 4; ++ntp) {
                    uint32_t b0e, b1e, b0o, b1o;
                    ldsm_x4(b0e, b1e, b0o, b1o,
                            vbase + (uint32_t)(((ntp * 16) * FT_LD + ks * 16) * 2));
                    mma_f16(o[2 * ntp],     pa[ks], b0e, b1e);
                    mma_f16(o[2 * ntp],     pl[ks], b0e, b1e);
                    mma_f16(o[2 * ntp + 1], pa[ks], b0o, b1o);
                    mma_f16(o[2 * ntp + 1], pl[ks], b0o, b1o);
                }
            }
        }
        __syncthreads();
    }

    // --- epilogue ---
    {
        const float r0v = 1.0f / l0;
        const float r1v = 1.0f / l1;
        float* Og = Out + (size_t)(b * SEQ + q0 + mb) * HDIM;
#pragma unroll
        for (int nto = 0; nto < 8; ++nto) {
            const int col = nto * 8 + c_fr;
            float2 v0, v1;
            v0.x = o[nto][0] * r0v; v0.y = o[nto][1] * r0v;
            v1.x = o[nto][2] * r1v; v1.y = o[nto][3] * r1v;
            *(float2*)(Og + (size_t)r_fr * HDIM + col)       = v0;
            *(float2*)(Og + (size_t)(r_fr + 8) * HDIM + col) = v1;
        }
    }
}

// ---------------------------------------------------------------------------
extern "C" void kernel_launch(void* const* d_in, const int* in_sizes, int n_in,
                              void* d_out, int out_size)
{
    const float* X  = (const float*)d_in[0];   // [512,256,384]
    const float* Wk = (const float*)d_in[1];   // [384,64]
    const float* Wq = (const float*)d_in[2];   // [384,64]
    const float* Wv = (const float*)d_in[3];   // [384,64]
    float* Out = (float*)d_out;                // [512,256,64]

    (void)in_sizes; (void)n_in; (void)out_size;

    cudaFuncSetAttribute(proj_kernel,
                         cudaFuncAttributeMaxDynamicSharedMemorySize, PJ_SMEM_BYTES);
    cudaFuncSetAttribute(attn_kernel,
                         cudaFuncAttributeMaxDynamicSharedMemorySize, AT_SMEM_BYTES);

    wconv_kernel<<<288, 256>>>(Wq, Wk, Wv);
    proj_kernel<<<NROWS / 128, 256, PJ_SMEM_BYTES>>>(X);

    dim3 grid(2, BATCH);
    attn_kernel<<<grid, 256, AT_SMEM_BYTES>>>(Out);
}

// round 13
// speedup vs baseline: 3.0822x; 1.3775x over previous
#include <cuda_runtime.h>
#include <cuda_fp16.h>
#include <cstdint>

#define BATCH 512
#define SEQ   256
#define EMBED 384
#define HDIM  64
#define NROWS (BATCH * SEQ)   // 131072

typedef uint16_t half_t;

// ---------------------------------------------------------------------------
// Global scratch (fp16, single precision-pass everywhere):
//   Qh: [b][s][d] fp16, PRE-SCALED by 1/8 (A operand of S)
//   Kh: [b][s][d] fp16 (B operand of S)
//   Vth:[b][d][s] fp16 (B operand of PV)
//   Wh: [mat][n][k] fp16
// ---------------------------------------------------------------------------
__device__ half_t g_Qh[(size_t)NROWS * HDIM];
__device__ half_t g_Kh[(size_t)NROWS * HDIM];
__device__ half_t g_Vth[(size_t)BATCH * HDIM * SEQ];
__device__ half_t g_Wh[3 * HDIM * EMBED];

// ---------------------------------------------------------------------------
__device__ __forceinline__ void mma_f16(float* d, const uint32_t* a,
                                        uint32_t b0, uint32_t b1) {
    asm volatile(
        "mma.sync.aligned.m16n8k16.row.col.f32.f16.f16.f32 "
        "{%0,%1,%2,%3}, {%4,%5,%6,%7}, {%8,%9}, {%0,%1,%2,%3};"
        : "+f"(d[0]), "+f"(d[1]), "+f"(d[2]), "+f"(d[3])
        : "r"(a[0]), "r"(a[1]), "r"(a[2]), "r"(a[3]), "r"(b0), "r"(b1));
}

__device__ __forceinline__ void ldsm_x4(uint32_t& r0, uint32_t& r1,
                                        uint32_t& r2, uint32_t& r3,
                                        uint32_t addr) {
    asm volatile(
        "ldmatrix.sync.aligned.m8n8.x4.shared.b16 {%0,%1,%2,%3}, [%4];"
        : "=r"(r0), "=r"(r1), "=r"(r2), "=r"(r3) : "r"(addr));
}

__device__ __forceinline__ uint32_t pack2h(float x, float y) {
    const __half2 hh = __floats2half2_rn(x, y);
    return *(const uint32_t*)&hh;
}

// ---------------------------------------------------------------------------
// W convert: fp32 [k][n] -> fp16 [mat][n][k]
// ---------------------------------------------------------------------------
__global__ void wconv_kernel(const float* __restrict__ Wq,
                             const float* __restrict__ Wk,
                             const float* __restrict__ Wv)
{
    const int idx = blockIdx.x * 256 + threadIdx.x;   // 73728
    const int mat = idx / (HDIM * EMBED);
    const int rem = idx % (HDIM * EMBED);
    const int n = rem / EMBED;
    const int k = rem % EMBED;
    const float* W = (mat == 0) ? Wq : ((mat == 1) ? Wk : Wv);
    const __half h = __float2half_rn(W[(size_t)k * HDIM + n]);
    g_Wh[idx] = *(const half_t*)&h;
}

// ---------------------------------------------------------------------------
// Projection: M=128, N=192 (Q|K|V), K=384 in 6 chunks of 64.
// Single-pass fp16. Double-buffered; ldmatrix fragments.
// ---------------------------------------------------------------------------
#define AK_LD 72
#define OFF_A  0
#define OFF_B  (128 * AK_LD)
#define CH_HALVES (OFF_B + 192 * AK_LD)        // 23040 halves / buffer
#define ST_LD 196
#define PJ_SMEM_BYTES (128 * ST_LD * 4 > 2 * CH_HALVES * 2 ? 128 * ST_LD * 4 : 2 * CH_HALVES * 2)

__global__ __launch_bounds__(256) void proj_kernel(const float* __restrict__ X)
{
    extern __shared__ char smraw[];
    float* stage = (float*)smraw;
    const uint32_t smb = (uint32_t)__cvta_generic_to_shared(smraw);

    const int tid = threadIdx.x;
    const int lane = tid & 31;
    const int wid = tid >> 5;
    const int warp_m = wid & 3;
    const int warp_n = wid >> 2;
    const int row0 = blockIdx.x * 128;

    const int r_fr = lane >> 2;
    const int c_fr = (lane & 3) * 2;
    const int bli = lane & 7;
    const int bsel = lane >> 3;
    const uint32_t a_lane =
        (uint32_t)((((bsel & 1) * 8 + bli) * AK_LD + (bsel >> 1) * 8) * 2);
    const uint32_t b_lane =
        (uint32_t)((((bsel >> 1) * 8 + bli) * AK_LD + (bsel & 1) * 8) * 2);

    float acc[2][12][4];
#pragma unroll
    for (int mt = 0; mt < 2; ++mt)
#pragma unroll
        for (int nt = 0; nt < 12; ++nt)
#pragma unroll
            for (int i = 0; i < 4; ++i) acc[mt][nt][i] = 0.0f;

    auto ldg_x = [&](int c, float4* xr) {
#pragma unroll
        for (int i = 0; i < 8; ++i) {
            const int idx = i * 256 + tid;
            const int m = idx >> 4;
            const int c4 = (idx & 15) * 4;
            xr[i] = *(const float4*)(X + (size_t)(row0 + m) * EMBED + c * 64 + c4);
        }
    };
    auto sts_x = [&](const float4* xr, int part) {
        half_t* A = (half_t*)smraw + part * CH_HALVES + OFF_A;
#pragma unroll
        for (int i = 0; i < 8; ++i) {
            const int idx = i * 256 + tid;
            const int m = idx >> 4;
            const int c4 = (idx & 15) * 4;
            uint2 hv;
            hv.x = pack2h(xr[i].x, xr[i].y);
            hv.y = pack2h(xr[i].z, xr[i].w);
            *(uint2*)(A + m * AK_LD + c4) = hv;
        }
    };
    auto ldg_sts_w = [&](int c, int part) {
        half_t* B = (half_t*)smraw + part * CH_HALVES + OFF_B;
#pragma unroll
        for (int i = 0; i < 6; ++i) {
            const int idx = i * 256 + tid;
            const int n = idx >> 3;
            const int q = idx & 7;
            const size_t gb = (size_t)n * EMBED + c * 64 + q * 8;
            *(float4*)(B + n * AK_LD + q * 8) = *(const float4*)(g_Wh + gb);
        }
    };

    {
        float4 xr[8];
        ldg_x(0, xr);
        sts_x(xr, 0);
        ldg_sts_w(0, 0);
    }
    __syncthreads();

    for (int c = 0; c < 6; ++c) {
        const int p = c & 1;
        const bool pf = (c < 5);
        float4 xr[8];
        if (pf) ldg_x(c + 1, xr);

        const uint32_t base = smb + (uint32_t)(p * CH_HALVES * 2);
        const uint32_t aB = base + a_lane;
        const uint32_t bB = base + (uint32_t)(OFF_B * 2) + b_lane;

#pragma unroll
        for (int ks = 0; ks < 4; ++ks) {
            const uint32_t kso = (uint32_t)(ks * 32);
            uint32_t a0[4], a1[4];
            ldsm_x4(a0[0], a0[1], a0[2], a0[3],
                    aB + (uint32_t)((warp_m * 32) * AK_LD * 2) + kso);
            ldsm_x4(a1[0], a1[1], a1[2], a1[3],
                    aB + (uint32_t)((warp_m * 32 + 16) * AK_LD * 2) + kso);
#pragma unroll
            for (int ntp = 0; ntp < 6; ++ntp) {
                uint32_t b0e, b1e, b0o, b1o;
                ldsm_x4(b0e, b1e, b0o, b1o,
                        bB + (uint32_t)(((warp_n * 96 + ntp * 16) * AK_LD) * 2) + kso);
                mma_f16(acc[0][2 * ntp],     a0, b0e, b1e);
                mma_f16(acc[1][2 * ntp],     a1, b0e, b1e);
                mma_f16(acc[0][2 * ntp + 1], a0, b0o, b1o);
                mma_f16(acc[1][2 * ntp + 1], a1, b0o, b1o);
            }
        }

        if (pf) {
            sts_x(xr, 1 - p);
            ldg_sts_w(c + 1, 1 - p);
        }
        __syncthreads();
    }

    // --- stage accumulators (fp32) ---
#pragma unroll
    for (int mt = 0; mt < 2; ++mt) {
        const int r0 = warp_m * 32 + mt * 16 + r_fr;
#pragma unroll
        for (int nt = 0; nt < 12; ++nt) {
            const int col = warp_n * 96 + nt * 8 + c_fr;
            float2 v0, v1;
            v0.x = acc[mt][nt][0]; v0.y = acc[mt][nt][1];
            v1.x = acc[mt][nt][2]; v1.y = acc[mt][nt][3];
            *(float2*)(stage + r0 * ST_LD + col)       = v0;
            *(float2*)(stage + (r0 + 8) * ST_LD + col) = v1;
        }
    }
    __syncthreads();

    const int b = row0 >> 8;
    const int sbase = row0 & 255;

    // --- Q fp16 PRE-SCALED by 1/8; K fp16: [b][s][d] ---
    for (int idx = tid; idx < 2048; idx += 256) {
        const int m = idx >> 4;
        const int q = (idx & 15) * 4;
        const size_t go = (size_t)(row0 + m) * HDIM + q;
        {
            const float4 v = *(const float4*)(stage + m * ST_LD + q);
            uint2 qv;
            qv.x = pack2h(v.x * 0.125f, v.y * 0.125f);
            qv.y = pack2h(v.z * 0.125f, v.w * 0.125f);
            *(uint2*)(g_Qh + go) = qv;
        }
        {
            const float4 v = *(const float4*)(stage + m * ST_LD + 64 + q);
            uint2 kv;
            kv.x = pack2h(v.x, v.y);
            kv.y = pack2h(v.z, v.w);
            *(uint2*)(g_Kh + go) = kv;
        }
    }
    // --- V fp16 transposed [b][d][s] ---
    for (int idx = tid; idx < 2048; idx += 256) {
        const int d = idx >> 5;
        const int s0 = (idx & 31) * 4;
        const float v0 = stage[(s0 + 0) * ST_LD + 128 + d];
        const float v1 = stage[(s0 + 1) * ST_LD + 128 + d];
        const float v2 = stage[(s0 + 2) * ST_LD + 128 + d];
        const float v3 = stage[(s0 + 3) * ST_LD + 128 + d];
        uint2 vv;
        vv.x = pack2h(v0, v1);
        vv.y = pack2h(v2, v3);
        *(uint2*)(g_Vth + ((size_t)b * HDIM + d) * SEQ + sbase + s0) = vv;
    }
}

// ---------------------------------------------------------------------------
// FlashAttention-2, single-pass fp16, occupancy 2 (smem 36.9KB, regs <=128).
// ---------------------------------------------------------------------------
#define FT_LD 72
#define BUF_HALVES (2 * 64 * FT_LD)           // Kh,Vh = 9216 halves
#define AT_SMEM_BYTES (2 * BUF_HALVES * 2)    // 36864 bytes

__global__ __launch_bounds__(256, 2) void attn_kernel(float* __restrict__ Out)
{
    extern __shared__ char smr[];
    half_t* const buf[2] = { (half_t*)smr, (half_t*)smr + BUF_HALVES };

    const int tid = threadIdx.x;
    const int lane = tid & 31;
    const int wid = tid >> 5;
    const int r_fr = lane >> 2;
    const int c_fr = (lane & 3) * 2;
    const int mb = wid * 16;

    const int qt = blockIdx.x;          // 0..1
    const int b  = blockIdx.y;
    const int q0 = qt * 128;
    const int njt = qt * 2 + 2;

    // --- stage Q (hi only), extract A-frags into registers ---
    uint32_t qh[4][4];
    {
        half_t* Qs = buf[0];
        const half_t* Qhg = g_Qh + (size_t)(b * SEQ + q0) * HDIM;
        for (int idx = tid; idx < 1024; idx += 256) {
            const int r = idx >> 3;
            const int q8 = (idx & 7) * 8;
            *(float4*)(Qs + r * FT_LD + q8) = *(const float4*)(Qhg + r * HDIM + q8);
        }
        __syncthreads();
#pragma unroll
        for (int ks = 0; ks < 4; ++ks) {
            const int kc = ks * 16 + c_fr;
            qh[ks][0] = *(const uint32_t*)(Qs + (mb + r_fr) * FT_LD + kc);
            qh[ks][1] = *(const uint32_t*)(Qs + (mb + r_fr + 8) * FT_LD + kc);
            qh[ks][2] = *(const uint32_t*)(Qs + (mb + r_fr) * FT_LD + kc + 8);
            qh[ks][3] = *(const uint32_t*)(Qs + (mb + r_fr + 8) * FT_LD + kc + 8);
        }
        __syncthreads();
    }

    float o[8][4];
#pragma unroll
    for (int nt = 0; nt < 8; ++nt)
#pragma unroll
        for (int i = 0; i < 4; ++i) o[nt][i] = 0.0f;
    float m0 = -3.4e38f, m1 = -3.4e38f, l0 = 0.0f, l1 = 0.0f;

    const half_t* Khg = g_Kh + (size_t)b * SEQ * HDIM;
    const half_t* Vhg = g_Vth + (size_t)b * HDIM * SEQ;

    auto load_tile = [&](int jt, half_t* dst) {
        half_t* Kh = dst;
        half_t* Vh = dst + 64 * FT_LD;
        const half_t* kh = Khg + (size_t)jt * 64 * HDIM;
        const half_t* vh = Vhg + jt * 64;
        for (int idx = tid; idx < 512; idx += 256) {
            const int r = idx >> 3;
            const int q8 = (idx & 7) * 8;
            *(float4*)(Kh + r * FT_LD + q8) = *(const float4*)(kh + r * HDIM + q8);
            *(float4*)(Vh + r * FT_LD + q8) = *(const float4*)(vh + (size_t)r * SEQ + q8);
        }
    };

    load_tile(0, buf[0]);
    __syncthreads();

    const int bli = lane & 7;
    const int bsel = lane >> 3;
    const uint32_t b_lane =
        (uint32_t)((((bsel >> 1) * 8 + bli) * FT_LD + (bsel & 1) * 8) * 2);

    for (int jt = 0; jt < njt; ++jt) {
        half_t* cur = buf[jt & 1];
        if (jt + 1 < njt) load_tile(jt + 1, buf[(jt + 1) & 1]);

        const bool active = (jt * 64) <= (q0 + mb + 15);
        if (active) {
            const uint32_t kbase = (uint32_t)__cvta_generic_to_shared(cur) + b_lane;
            const uint32_t vbase = kbase + (uint32_t)(64 * FT_LD * 2);

            // --- S = Q K^T (single pass; scale pre-folded) ---
            float s[8][4];
#pragma unroll
            for (int nt = 0; nt < 8; ++nt)
#pragma unroll
                for (int i = 0; i < 4; ++i) s[nt][i] = 0.0f;
#pragma unroll
            for (int ks = 0; ks < 4; ++ks) {
#pragma unroll
                for (int ntp = 0; ntp < 4; ++ntp) {
                    uint32_t b0e, b1e, b0o, b1o;
                    ldsm_x4(b0e, b1e, b0o, b1o,
                            kbase + (uint32_t)(((ntp * 16) * FT_LD + ks * 16) * 2));
                    mma_f16(s[2 * ntp],     qh[ks], b0e, b1e);
                    mma_f16(s[2 * ntp + 1], qh[ks], b0o, b1o);
                }
            }

            // --- causal mask (diagonal tiles only) ---
            const int rowg0 = q0 + mb + r_fr;
            const int rowg1 = rowg0 + 8;
            if ((jt * 64 + 63) > (q0 + mb)) {
#pragma unroll
                for (int nt = 0; nt < 8; ++nt) {
                    const int colg = jt * 64 + nt * 8 + c_fr;
                    if (colg     > rowg0) s[nt][0] = -3.4e38f;
                    if (colg + 1 > rowg0) s[nt][1] = -3.4e38f;
                    if (colg     > rowg1) s[nt][2] = -3.4e38f;
                    if (colg + 1 > rowg1) s[nt][3] = -3.4e38f;
                }
            }

            // --- online softmax ---
            float mx0 = -3.4e38f, mx1 = -3.4e38f;
#pragma unroll
            for (int nt = 0; nt < 8; ++nt) {
                mx0 = fmaxf(mx0, fmaxf(s[nt][0], s[nt][1]));
                mx1 = fmaxf(mx1, fmaxf(s[nt][2], s[nt][3]));
            }
            mx0 = fmaxf(mx0, __shfl_xor_sync(0xffffffffu, mx0, 1));
            mx0 = fmaxf(mx0, __shfl_xor_sync(0xffffffffu, mx0, 2));
            mx1 = fmaxf(mx1, __shfl_xor_sync(0xffffffffu, mx1, 1));
            mx1 = fmaxf(mx1, __shfl_xor_sync(0xffffffffu, mx1, 2));
            const float mn0 = fmaxf(m0, mx0);
            const float mn1 = fmaxf(m1, mx1);
            const float a0 = __expf(m0 - mn0);
            const float a1 = __expf(m1 - mn1);
            l0 *= a0; l1 *= a1;
#pragma unroll
            for (int nt = 0; nt < 8; ++nt) {
                o[nt][0] *= a0; o[nt][1] *= a0;
                o[nt][2] *= a1; o[nt][3] *= a1;
            }
            m0 = mn0; m1 = mn1;

            // --- P = exp(S-m) -> fp16 A-frags (single) ---
            uint32_t pa[4][4];
            float sum0 = 0.0f, sum1 = 0.0f;
#pragma unroll
            for (int nt = 0; nt < 8; ++nt) {
                const float p0 = __expf(s[nt][0] - mn0);
                const float p1 = __expf(s[nt][1] - mn0);
                const float p2 = __expf(s[nt][2] - mn1);
                const float p3 = __expf(s[nt][3] - mn1);
                sum0 += p0 + p1;
                sum1 += p2 + p3;
                const int ks = nt >> 1;
                const int off = (nt & 1) * 2;
                pa[ks][off]     = pack2h(p0, p1);
                pa[ks][off + 1] = pack2h(p2, p3);
            }
            sum0 += __shfl_xor_sync(0xffffffffu, sum0, 1);
            sum0 += __shfl_xor_sync(0xffffffffu, sum0, 2);
            sum1 += __shfl_xor_sync(0xffffffffu, sum1, 1);
            sum1 += __shfl_xor_sync(0xffffffffu, sum1, 2);
            l0 += sum0; l1 += sum1;

            // --- O += P V (single pass) ---
#pragma unroll
            for (int ks = 0; ks < 4; ++ks) {
#pragma unroll
                for (int ntp = 0; ntp < 4; ++ntp) {
                    uint32_t b0e, b1e, b0o, b1o;
                    ldsm_x4(b0e, b1e, b0o, b1o,
                            vbase + (uint32_t)(((ntp * 16) * FT_LD + ks * 16) * 2));
                    mma_f16(o[2 * ntp],     pa[ks], b0e, b1e);
                    mma_f16(o[2 * ntp + 1], pa[ks], b0o, b1o);
                }
            }
        }
        __syncthreads();
    }

    // --- epilogue ---
    {
        const float r0v = 1.0f / l0;
        const float r1v = 1.0f / l1;
        float* Og = Out + (size_t)(b * SEQ + q0 + mb) * HDIM;
#pragma unroll
        for (int nto = 0; nto < 8; ++nto) {
            const int col = nto * 8 + c_fr;
            float2 v0, v1;
            v0.x = o[nto][0] * r0v; v0.y = o[nto][1] * r0v;
            v1.x = o[nto][2] * r1v; v1.y = o[nto][3] * r1v;
            *(float2*)(Og + (size_t)r_fr * HDIM + col)       = v0;
            *(float2*)(Og + (size_t)(r_fr + 8) * HDIM + col) = v1;
        }
    }
}

// ---------------------------------------------------------------------------
extern "C" void kernel_launch(void* const* d_in, const int* in_sizes, int n_in,
                              void* d_out, int out_size)
{
    const float* X  = (const float*)d_in[0];   // [512,256,384]
    const float* Wk = (const float*)d_in[1];   // [384,64]
    const float* Wq = (const float*)d_in[2];   // [384,64]
    const float* Wv = (const float*)d_in[3];   // [384,64]
    float* Out = (float*)d_out;                // [512,256,64]

    (void)in_sizes; (void)n_in; (void)out_size;

    cudaFuncSetAttribute(proj_kernel,
                         cudaFuncAttributeMaxDynamicSharedMemorySize, PJ_SMEM_BYTES);
    cudaFuncSetAttribute(attn_kernel,
                         cudaFuncAttributeMaxDynamicSharedMemorySize, AT_SMEM_BYTES);

    wconv_kernel<<<288, 256>>>(Wq, Wk, Wv);
    proj_kernel<<<NROWS / 128, 256, PJ_SMEM_BYTES>>>(X);

    dim3 grid(2, BATCH);
    attn_kernel<<<grid, 256, AT_SMEM_BYTES>>>(Out);
}